// round 2
// baseline (speedup 1.0000x reference)
#include <cuda_runtime.h>

// Problem constants
#define B_   2
#define SQ_  2048
#define DM_  1024
#define NH_  16
#define DH_  64
#define MROWS (B_*SQ_)          // 4096

// Scratch (no cudaMalloc allowed)
__device__ float g_q[(size_t)B_*SQ_*DM_];   // post-LN q, (b,s,n,h)
__device__ float g_z[(size_t)B_*SQ_*DM_];   // attention output z, (b,s,n,h)

// ---------------------------------------------------------------------------
// SGEMM with bias: C[M,N] = A[M,K] @ B + bias[N]
// B element (k, c) is at Bw[(c>>6)*headStride + k*rowStride + (c&63)]
//   projections (W is [NH, DM, DH]): headStride = 65536, rowStride = 64
//   output proj (W_O as [K=1024, N=1024] row-major): headStride = 64, rowStride = 1024
// ---------------------------------------------------------------------------
#define BM 128
#define BN 128
#define BKK 16

__global__ void __launch_bounds__(256)
gemm_bias_kernel(const float* __restrict__ A, const float* __restrict__ Bw,
                 const float* __restrict__ bias, float* __restrict__ C,
                 int K, int N, int headStride, int rowStride)
{
    __shared__ float As[BKK][BM];   // transposed A tile
    __shared__ float Bs[BKK][BN];

    const int tid = threadIdx.x;
    const int bm  = blockIdx.y * BM;
    const int bn  = blockIdx.x * BN;
    const int tx  = tid & 15;       // 0..15 -> 8 cols each
    const int ty  = tid >> 4;       // 0..15 -> 8 rows each

    float acc[8][8];
    #pragma unroll
    for (int i = 0; i < 8; i++)
        #pragma unroll
        for (int j = 0; j < 8; j++)
            acc[i][j] = 0.f;

    for (int k0 = 0; k0 < K; k0 += BKK) {
        // Load A tile: BM x BKK = 2048 floats = 512 float4, 2 per thread
        #pragma unroll
        for (int it = 0; it < 2; it++) {
            int idx = tid + it * 256;          // float4 index
            int m   = idx >> 2;                // 0..127
            int kq  = idx & 3;                 // float4 within row
            float4 va = *(const float4*)(A + (size_t)(bm + m) * K + k0 + kq * 4);
            As[kq*4+0][m] = va.x;
            As[kq*4+1][m] = va.y;
            As[kq*4+2][m] = va.z;
            As[kq*4+3][m] = va.w;
        }
        // Load B tile: BKK x BN = 2048 floats = 512 float4, 2 per thread
        #pragma unroll
        for (int it = 0; it < 2; it++) {
            int idx = tid + it * 256;
            int kk  = idx >> 5;                // 0..15
            int nq  = (idx & 31) << 2;         // 0..124
            int c   = bn + nq;
            const float* bp = Bw + (size_t)(c >> 6) * headStride
                                 + (size_t)(k0 + kk) * rowStride + (c & 63);
            *(float4*)&Bs[kk][nq] = *(const float4*)bp;
        }
        __syncthreads();

        #pragma unroll
        for (int kk = 0; kk < BKK; kk++) {
            float af[8], bf[8];
            #pragma unroll
            for (int i = 0; i < 8; i++) af[i] = As[kk][ty*8 + i];
            #pragma unroll
            for (int j = 0; j < 8; j++) bf[j] = Bs[kk][tx*8 + j];
            #pragma unroll
            for (int i = 0; i < 8; i++)
                #pragma unroll
                for (int j = 0; j < 8; j++)
                    acc[i][j] += af[i] * bf[j];
        }
        __syncthreads();
    }

    // Epilogue + bias
    #pragma unroll
    for (int i = 0; i < 8; i++) {
        int row = bm + ty*8 + i;
        float* cp = C + (size_t)row * N + bn + tx*8;
        const float* bp = bias + bn + tx*8;
        float4 o0, o1;
        o0.x = acc[i][0] + bp[0];  o0.y = acc[i][1] + bp[1];
        o0.z = acc[i][2] + bp[2];  o0.w = acc[i][3] + bp[3];
        o1.x = acc[i][4] + bp[4];  o1.y = acc[i][5] + bp[5];
        o1.z = acc[i][6] + bp[6];  o1.w = acc[i][7] + bp[7];
        *(float4*)(cp)     = o0;
        *(float4*)(cp + 4) = o1;
    }
}

// ---------------------------------------------------------------------------
// Per-head LayerNorm over d_head=64, in place. One warp per (b,s,n) row.
// blockIdx.y == 0 -> q buffer with ln1; == 1 -> k buffer with ln2.
// ---------------------------------------------------------------------------
__global__ void __launch_bounds__(256)
ln_kernel(float* __restrict__ qb, float* __restrict__ kb,
          const float* __restrict__ w1, const float* __restrict__ b1,
          const float* __restrict__ w2, const float* __restrict__ b2)
{
    const int warp = threadIdx.x >> 5;
    const int lane = threadIdx.x & 31;
    const int row  = blockIdx.x * 8 + warp;            // 0 .. 65535

    float* base       = (blockIdx.y == 0) ? qb : kb;
    const float* w    = (blockIdx.y == 0) ? w1 : w2;
    const float* bb   = (blockIdx.y == 0) ? b1 : b2;

    float* p = base + (size_t)row * DH_;
    float x0 = p[lane];
    float x1 = p[lane + 32];
    float s  = x0 + x1;
    float sq = x0*x0 + x1*x1;
    #pragma unroll
    for (int o = 16; o > 0; o >>= 1) {
        s  += __shfl_xor_sync(0xffffffffu, s,  o);
        sq += __shfl_xor_sync(0xffffffffu, sq, o);
    }
    float mean = s * (1.0f/64.0f);
    float var  = sq * (1.0f/64.0f) - mean*mean;
    float rstd = rsqrtf(var + 1e-5f);
    p[lane]      = (x0 - mean) * rstd * w[lane]      + bb[lane];
    p[lane + 32] = (x1 - mean) * rstd * w[lane + 32] + bb[lane + 32];
}

// ---------------------------------------------------------------------------
// Causal flash attention, fp32, no 1/sqrt(d) scaling (matches reference).
// One query row per thread; 128 threads/CTA; K/V tiles (64x64) in SMEM.
// grid = (SQ/128, NH, B)
// ---------------------------------------------------------------------------
__global__ void __launch_bounds__(128)
attn_kernel(const float* __restrict__ q, const float* __restrict__ k,
            const float* __restrict__ v, float* __restrict__ z)
{
    __shared__ float Ks[64][64];
    __shared__ float Vs[64][64];

    const int b = blockIdx.z;
    const int n = blockIdx.y;
    const int qrow = blockIdx.x * 128 + threadIdx.x;   // 0..2047

    const float* qp = q + (size_t)(b * SQ_ + qrow) * DM_ + n * DH_;
    float qr[64];
    #pragma unroll
    for (int i = 0; i < 16; i++) {
        float4 t = *(const float4*)(qp + i*4);
        qr[i*4+0] = t.x; qr[i*4+1] = t.y; qr[i*4+2] = t.z; qr[i*4+3] = t.w;
    }

    float acc[64];
    #pragma unroll
    for (int h = 0; h < 64; h++) acc[h] = 0.f;
    float m = -1e30f, l = 0.f;

    const int ntiles = blockIdx.x * 2 + 2;             // key tiles needed by this CTA
    for (int kt = 0; kt < ntiles; kt++) {
        const int kbase = b * SQ_ + kt * 64;
        #pragma unroll
        for (int i = 0; i < 8; i++) {
            int idx = threadIdx.x + i * 128;           // float4 index over 64x64 tile
            int j   = idx >> 4;
            int h4  = (idx & 15) << 2;
            const size_t off = (size_t)(kbase + j) * DM_ + n * DH_ + h4;
            *(float4*)&Ks[j][h4] = *(const float4*)(k + off);
            *(float4*)&Vs[j][h4] = *(const float4*)(v + off);
        }
        __syncthreads();

        int jmax = qrow - kt * 64 + 1;                 // causal bound in this tile
        if (jmax > 64) jmax = 64;
        for (int j = 0; j < jmax; j++) {
            const float4* Kj = (const float4*)&Ks[j][0];
            float s0 = 0.f, s1 = 0.f, s2 = 0.f, s3 = 0.f;
            #pragma unroll
            for (int h = 0; h < 16; h++) {
                float4 kk = Kj[h];
                s0 += qr[h*4+0] * kk.x;
                s1 += qr[h*4+1] * kk.y;
                s2 += qr[h*4+2] * kk.z;
                s3 += qr[h*4+3] * kk.w;
            }
            float sc = (s0 + s1) + (s2 + s3);
            float mn = fmaxf(m, sc);
            if (mn > m) {                              // rare after warmup: ~ln(SK) times
                float corr = __expf(m - mn);
                l *= corr;
                #pragma unroll
                for (int h = 0; h < 64; h++) acc[h] *= corr;
                m = mn;
            }
            float p = __expf(sc - mn);
            l += p;
            const float4* Vj = (const float4*)&Vs[j][0];
            #pragma unroll
            for (int h = 0; h < 16; h++) {
                float4 vv = Vj[h];
                acc[h*4+0] += p * vv.x;
                acc[h*4+1] += p * vv.y;
                acc[h*4+2] += p * vv.z;
                acc[h*4+3] += p * vv.w;
            }
        }
        __syncthreads();
    }

    float inv = 1.0f / l;
    float* zp = z + (size_t)(b * SQ_ + qrow) * DM_ + n * DH_;
    #pragma unroll
    for (int h = 0; h < 16; h++) {
        float4 o;
        o.x = acc[h*4+0] * inv; o.y = acc[h*4+1] * inv;
        o.z = acc[h*4+2] * inv; o.w = acc[h*4+3] * inv;
        *(float4*)(zp + h*4) = o;
    }
}

// ---------------------------------------------------------------------------
// Launch. Inputs (metadata order):
// 0 x_q, 1 x_kv, 2 mask (ignored: causal computed directly), 3 W_Q, 4 W_K,
// 5 W_V, 6 W_O, 7 b_Q, 8 b_K, 9 b_V, 10 b_O, 11 ln1_w, 12 ln1_b, 13 ln2_w, 14 ln2_b
// Output: [out (B,SQ,DM) | k_postLN (B,SK,NH,DH) | v (B,SK,NH,DH)]
// ---------------------------------------------------------------------------
extern "C" void kernel_launch(void* const* d_in, const int* in_sizes, int n_in,
                              void* d_out, int out_size)
{
    const float* x_q  = (const float*)d_in[0];
    const float* x_kv = (const float*)d_in[1];
    const float* W_Q  = (const float*)d_in[3];
    const float* W_K  = (const float*)d_in[4];
    const float* W_V  = (const float*)d_in[5];
    const float* W_O  = (const float*)d_in[6];
    const float* b_Q  = (const float*)d_in[7];
    const float* b_K  = (const float*)d_in[8];
    const float* b_V  = (const float*)d_in[9];
    const float* b_O  = (const float*)d_in[10];
    const float* ln1w = (const float*)d_in[11];
    const float* ln1b = (const float*)d_in[12];
    const float* ln2w = (const float*)d_in[13];
    const float* ln2b = (const float*)d_in[14];

    float* out  = (float*)d_out;
    float* kout = out  + (size_t)B_*SQ_*DM_;
    float* vout = kout + (size_t)B_*SQ_*DM_;

    float* qbuf = nullptr;
    float* zbuf = nullptr;
    cudaGetSymbolAddress((void**)&qbuf, g_q);
    cudaGetSymbolAddress((void**)&zbuf, g_z);

    dim3 gg(DM_/BN, MROWS/BM);   // (8, 32)

    // QKV projections (+bias). k and v land directly in their output slots.
    gemm_bias_kernel<<<gg, 256>>>(x_q,  W_Q, b_Q, qbuf, DM_, DM_, DM_*DH_, DH_);
    gemm_bias_kernel<<<gg, 256>>>(x_kv, W_K, b_K, kout, DM_, DM_, DM_*DH_, DH_);
    gemm_bias_kernel<<<gg, 256>>>(x_kv, W_V, b_V, vout, DM_, DM_, DM_*DH_, DH_);

    // Per-head LN in place: q with ln1, k with ln2 (reference returns post-LN k).
    ln_kernel<<<dim3((MROWS*NH_)/8, 2), 256>>>(qbuf, kout, ln1w, ln1b, ln2w, ln2b);

    // Causal attention -> z
    attn_kernel<<<dim3(SQ_/128, NH_, B_), 128>>>(qbuf, kout, vout, zbuf);

    // Output projection (+b_O)
    gemm_bias_kernel<<<gg, 256>>>(zbuf, W_O, b_O, out, DM_, DM_, DH_, DM_);
}

// round 3
// speedup vs baseline: 1.0601x; 1.0601x over previous
#include <cuda_runtime.h>

// Problem constants
#define B_   2
#define SQ_  2048
#define DM_  1024
#define NH_  16
#define DH_  64
#define MROWS (B_*SQ_)          // 4096

// Scratch (no cudaMalloc allowed)
__device__ float g_q[(size_t)B_*SQ_*DM_];   // post-LN q, (b,s,n,h)
__device__ float g_z[(size_t)B_*SQ_*DM_];   // attention output z, (b,s,n,h)

// ---------------- packed f32x2 helpers (sm_100+) ----------------
typedef unsigned long long u64t;

__device__ __forceinline__ u64t fma2(u64t a, u64t b, u64t c) {
    u64t d;
    asm("fma.rn.f32x2 %0, %1, %2, %3;" : "=l"(d) : "l"(a), "l"(b), "l"(c));
    return d;
}
__device__ __forceinline__ u64t mul2(u64t a, u64t b) {
    u64t d;
    asm("mul.rn.f32x2 %0, %1, %2;" : "=l"(d) : "l"(a), "l"(b));
    return d;
}
__device__ __forceinline__ u64t dup2(float x) {
    u64t d;
    asm("mov.b64 %0, {%1, %1};" : "=l"(d) : "f"(x));
    return d;
}
union F4U { float4 f; u64t u[2]; float s[4]; };
union U2F { u64t u; float s[2]; };

// ---------------------------------------------------------------------------
// SGEMM with bias: C[M,N] = A[M,K] @ B + bias[N]   (packed f32x2 inner loop)
// B element (k, c) is at Bw[(c>>6)*headStride + k*rowStride + (c&63)]
// ---------------------------------------------------------------------------
#define BM 128
#define BN 128
#define BKK 16

__global__ void __launch_bounds__(256)
gemm_bias_kernel(const float* __restrict__ A, const float* __restrict__ Bw,
                 const float* __restrict__ bias, float* __restrict__ C,
                 int K, int N, int headStride, int rowStride)
{
    __shared__ float As[BKK][BM];   // transposed A tile
    __shared__ float Bs[BKK][BN];

    const int tid = threadIdx.x;
    const int bm  = blockIdx.y * BM;
    const int bn  = blockIdx.x * BN;
    const int tx  = tid & 15;       // 0..15 -> 8 cols each
    const int ty  = tid >> 4;       // 0..15 -> 8 rows each

    u64t acc2[8][4];                // [row i][col pair j2], packed 2 cols
    #pragma unroll
    for (int i = 0; i < 8; i++)
        #pragma unroll
        for (int j = 0; j < 4; j++)
            acc2[i][j] = 0ull;

    for (int k0 = 0; k0 < K; k0 += BKK) {
        // Load A tile: BM x BKK = 512 float4, 2 per thread (transposed store)
        #pragma unroll
        for (int it = 0; it < 2; it++) {
            int idx = tid + it * 256;
            int m   = idx >> 2;
            int kq  = idx & 3;
            float4 va = *(const float4*)(A + (size_t)(bm + m) * K + k0 + kq * 4);
            As[kq*4+0][m] = va.x;
            As[kq*4+1][m] = va.y;
            As[kq*4+2][m] = va.z;
            As[kq*4+3][m] = va.w;
        }
        // Load B tile: BKK x BN = 512 float4, 2 per thread
        #pragma unroll
        for (int it = 0; it < 2; it++) {
            int idx = tid + it * 256;
            int kk  = idx >> 5;
            int nq  = (idx & 31) << 2;
            int c   = bn + nq;
            const float* bp = Bw + (size_t)(c >> 6) * headStride
                                 + (size_t)(k0 + kk) * rowStride + (c & 63);
            *(float4*)&Bs[kk][nq] = *(const float4*)bp;
        }
        __syncthreads();

        #pragma unroll
        for (int kk = 0; kk < BKK; kk++) {
            F4U a0, a1, b0, b1;
            a0.f = *(const float4*)&As[kk][ty*8];
            a1.f = *(const float4*)&As[kk][ty*8 + 4];
            b0.f = *(const float4*)&Bs[kk][tx*8];
            b1.f = *(const float4*)&Bs[kk][tx*8 + 4];
            u64t b2[4] = { b0.u[0], b0.u[1], b1.u[0], b1.u[1] };
            u64t ad[8];
            ad[0] = dup2(a0.s[0]); ad[1] = dup2(a0.s[1]);
            ad[2] = dup2(a0.s[2]); ad[3] = dup2(a0.s[3]);
            ad[4] = dup2(a1.s[0]); ad[5] = dup2(a1.s[1]);
            ad[6] = dup2(a1.s[2]); ad[7] = dup2(a1.s[3]);
            #pragma unroll
            for (int i = 0; i < 8; i++)
                #pragma unroll
                for (int j = 0; j < 4; j++)
                    acc2[i][j] = fma2(ad[i], b2[j], acc2[i][j]);
        }
        __syncthreads();
    }

    // Epilogue + bias
    F4U bb0, bb1;
    bb0.f = *(const float4*)(bias + bn + tx*8);
    bb1.f = *(const float4*)(bias + bn + tx*8 + 4);
    #pragma unroll
    for (int i = 0; i < 8; i++) {
        int row = bm + ty*8 + i;
        float* cp = C + (size_t)row * N + bn + tx*8;
        F4U o0, o1;
        U2F t;
        t.u = acc2[i][0]; o0.s[0] = t.s[0] + bb0.s[0]; o0.s[1] = t.s[1] + bb0.s[1];
        t.u = acc2[i][1]; o0.s[2] = t.s[0] + bb0.s[2]; o0.s[3] = t.s[1] + bb0.s[3];
        t.u = acc2[i][2]; o1.s[0] = t.s[0] + bb1.s[0]; o1.s[1] = t.s[1] + bb1.s[1];
        t.u = acc2[i][3]; o1.s[2] = t.s[0] + bb1.s[2]; o1.s[3] = t.s[1] + bb1.s[3];
        *(float4*)(cp)     = o0.f;
        *(float4*)(cp + 4) = o1.f;
    }
}

// ---------------------------------------------------------------------------
// Per-head LayerNorm over d_head=64, in place. One warp per (b,s,n) row.
// ---------------------------------------------------------------------------
__global__ void __launch_bounds__(256)
ln_kernel(float* __restrict__ qb, float* __restrict__ kb,
          const float* __restrict__ w1, const float* __restrict__ b1,
          const float* __restrict__ w2, const float* __restrict__ b2)
{
    const int warp = threadIdx.x >> 5;
    const int lane = threadIdx.x & 31;
    const int row  = blockIdx.x * 8 + warp;

    float* base       = (blockIdx.y == 0) ? qb : kb;
    const float* w    = (blockIdx.y == 0) ? w1 : w2;
    const float* bb   = (blockIdx.y == 0) ? b1 : b2;

    float* p = base + (size_t)row * DH_;
    float x0 = p[lane];
    float x1 = p[lane + 32];
    float s  = x0 + x1;
    float sq = x0*x0 + x1*x1;
    #pragma unroll
    for (int o = 16; o > 0; o >>= 1) {
        s  += __shfl_xor_sync(0xffffffffu, s,  o);
        sq += __shfl_xor_sync(0xffffffffu, sq, o);
    }
    float mean = s * (1.0f/64.0f);
    float var  = sq * (1.0f/64.0f) - mean*mean;
    float rstd = rsqrtf(var + 1e-5f);
    p[lane]      = (x0 - mean) * rstd * w[lane]      + bb[lane];
    p[lane + 32] = (x1 - mean) * rstd * w[lane + 32] + bb[lane + 32];
}

// ---------------------------------------------------------------------------
// Causal flash attention, fp32 packed f32x2, no 1/sqrt(d) scaling.
// One query row per thread; 128 threads/CTA; K/V tiles (64x64) in SMEM.
// grid = (SQ/128, NH, B)
// ---------------------------------------------------------------------------
__global__ void __launch_bounds__(128)
attn_kernel(const float* __restrict__ q, const float* __restrict__ k,
            const float* __restrict__ v, float* __restrict__ z)
{
    __shared__ float Ks[64][64];
    __shared__ float Vs[64][64];

    const int b = blockIdx.z;
    const int n = blockIdx.y;
    const int qrow = blockIdx.x * 128 + threadIdx.x;

    // q row packed: 32 x f32x2
    u64t q2[32];
    {
        const float* qp = q + (size_t)(b * SQ_ + qrow) * DM_ + n * DH_;
        #pragma unroll
        for (int i = 0; i < 16; i++) {
            F4U t; t.f = *(const float4*)(qp + i*4);
            q2[2*i]   = t.u[0];
            q2[2*i+1] = t.u[1];
        }
    }

    u64t acc2[32];
    #pragma unroll
    for (int h = 0; h < 32; h++) acc2[h] = 0ull;
    float m = -1e30f, l = 0.f;

    const int ntiles = blockIdx.x * 2 + 2;
    for (int kt = 0; kt < ntiles; kt++) {
        const int kbase = b * SQ_ + kt * 64;
        #pragma unroll
        for (int i = 0; i < 8; i++) {
            int idx = threadIdx.x + i * 128;
            int j   = idx >> 4;
            int h4  = (idx & 15) << 2;
            const size_t off = (size_t)(kbase + j) * DM_ + n * DH_ + h4;
            *(float4*)&Ks[j][h4] = *(const float4*)(k + off);
            *(float4*)&Vs[j][h4] = *(const float4*)(v + off);
        }
        __syncthreads();

        int jmax = qrow - kt * 64 + 1;
        if (jmax > 64) jmax = 64;
        for (int j = 0; j < jmax; j++) {
            const float4* Kj = (const float4*)&Ks[j][0];
            u64t s2[4] = {0ull, 0ull, 0ull, 0ull};
            #pragma unroll
            for (int t = 0; t < 16; t++) {
                F4U kk4; kk4.f = Kj[t];
                s2[(2*t)   & 3] = fma2(q2[2*t],   kk4.u[0], s2[(2*t)   & 3]);
                s2[(2*t+1) & 3] = fma2(q2[2*t+1], kk4.u[1], s2[(2*t+1) & 3]);
            }
            U2F u0, u1, u2, u3;
            u0.u = s2[0]; u1.u = s2[1]; u2.u = s2[2]; u3.u = s2[3];
            float sc = ((u0.s[0] + u0.s[1]) + (u1.s[0] + u1.s[1]))
                     + ((u2.s[0] + u2.s[1]) + (u3.s[0] + u3.s[1]));

            float mn = fmaxf(m, sc);
            if (mn > m) {                          // rare after warmup
                u64t cd = dup2(__expf(m - mn));
                U2F c; c.u = cd;
                l *= c.s[0];
                #pragma unroll
                for (int h = 0; h < 32; h++) acc2[h] = mul2(cd, acc2[h]);
                m = mn;
            }
            float p = __expf(sc - mn);
            l += p;
            u64t pd = dup2(p);
            const float4* Vj = (const float4*)&Vs[j][0];
            #pragma unroll
            for (int t = 0; t < 16; t++) {
                F4U vv4; vv4.f = Vj[t];
                acc2[2*t]   = fma2(pd, vv4.u[0], acc2[2*t]);
                acc2[2*t+1] = fma2(pd, vv4.u[1], acc2[2*t+1]);
            }
        }
        __syncthreads();
    }

    u64t ivd = dup2(1.0f / l);
    float* zp = z + (size_t)(b * SQ_ + qrow) * DM_ + n * DH_;
    #pragma unroll
    for (int t = 0; t < 16; t++) {
        F4U o;
        o.u[0] = mul2(ivd, acc2[2*t]);
        o.u[1] = mul2(ivd, acc2[2*t+1]);
        *(float4*)(zp + t*4) = o.f;
    }
}

// ---------------------------------------------------------------------------
// Launch. Inputs (metadata order):
// 0 x_q, 1 x_kv, 2 mask (ignored: causal computed directly), 3 W_Q, 4 W_K,
// 5 W_V, 6 W_O, 7 b_Q, 8 b_K, 9 b_V, 10 b_O, 11 ln1_w, 12 ln1_b, 13 ln2_w, 14 ln2_b
// Output: [out (B,SQ,DM) | k_postLN (B,SK,NH,DH) | v (B,SK,NH,DH)]
// ---------------------------------------------------------------------------
extern "C" void kernel_launch(void* const* d_in, const int* in_sizes, int n_in,
                              void* d_out, int out_size)
{
    const float* x_q  = (const float*)d_in[0];
    const float* x_kv = (const float*)d_in[1];
    const float* W_Q  = (const float*)d_in[3];
    const float* W_K  = (const float*)d_in[4];
    const float* W_V  = (const float*)d_in[5];
    const float* W_O  = (const float*)d_in[6];
    const float* b_Q  = (const float*)d_in[7];
    const float* b_K  = (const float*)d_in[8];
    const float* b_V  = (const float*)d_in[9];
    const float* b_O  = (const float*)d_in[10];
    const float* ln1w = (const float*)d_in[11];
    const float* ln1b = (const float*)d_in[12];
    const float* ln2w = (const float*)d_in[13];
    const float* ln2b = (const float*)d_in[14];

    float* out  = (float*)d_out;
    float* kout = out  + (size_t)B_*SQ_*DM_;
    float* vout = kout + (size_t)B_*SQ_*DM_;

    float* qbuf = nullptr;
    float* zbuf = nullptr;
    cudaGetSymbolAddress((void**)&qbuf, g_q);
    cudaGetSymbolAddress((void**)&zbuf, g_z);

    dim3 gg(DM_/BN, MROWS/BM);   // (8, 32)

    // QKV projections (+bias). k and v land directly in their output slots.
    gemm_bias_kernel<<<gg, 256>>>(x_q,  W_Q, b_Q, qbuf, DM_, DM_, DM_*DH_, DH_);
    gemm_bias_kernel<<<gg, 256>>>(x_kv, W_K, b_K, kout, DM_, DM_, DM_*DH_, DH_);
    gemm_bias_kernel<<<gg, 256>>>(x_kv, W_V, b_V, vout, DM_, DM_, DM_*DH_, DH_);

    // Per-head LN in place: q with ln1, k with ln2.
    ln_kernel<<<dim3((MROWS*NH_)/8, 2), 256>>>(qbuf, kout, ln1w, ln1b, ln2w, ln2b);

    // Causal attention -> z
    attn_kernel<<<dim3(SQ_/128, NH_, B_), 128>>>(qbuf, kout, vout, zbuf);

    // Output projection (+b_O)
    gemm_bias_kernel<<<gg, 256>>>(zbuf, W_O, b_O, out, DM_, DM_, DH_, DM_);
}

// round 5
// speedup vs baseline: 1.0852x; 1.0236x over previous
#include <cuda_runtime.h>
#include <cuda_bf16.h>
#include <cstdint>

// Problem constants
#define B_   2
#define SQ_  2048
#define DM_  1024
#define NH_  16
#define DH_  64
#define MROWS (B_*SQ_)          // 4096

// Scratch (no cudaMalloc allowed)
__device__ float g_q[(size_t)B_*SQ_*DM_];   // post-LN q, (b,s,n,h)
__device__ float g_z[(size_t)B_*SQ_*DM_];   // attention output z, (b,s,n,h)

// ---------------- packed f32x2 helpers ----------------
typedef unsigned long long u64t;
__device__ __forceinline__ u64t fma2(u64t a, u64t b, u64t c) {
    u64t d; asm("fma.rn.f32x2 %0, %1, %2, %3;" : "=l"(d) : "l"(a), "l"(b), "l"(c)); return d;
}
__device__ __forceinline__ u64t mul2(u64t a, u64t b) {
    u64t d; asm("mul.rn.f32x2 %0, %1, %2;" : "=l"(d) : "l"(a), "l"(b)); return d;
}
__device__ __forceinline__ u64t dup2(float x) {
    u64t d; asm("mov.b64 %0, {%1, %1};" : "=l"(d) : "f"(x)); return d;
}
union F4U { float4 f; u64t u[2]; float s[4]; };
union U2F { u64t u; float s[2]; };

// ---------------- mma.sync helpers (baseline PTX, runs on HMMA pipe) -------
__device__ __forceinline__ uint32_t smem_u32(const void* p) {
    uint32_t a;
    asm("{ .reg .u64 t; cvta.to.shared.u64 t, %1; cvt.u32.u64 %0, t; }" : "=r"(a) : "l"(p));
    return a;
}
__device__ __forceinline__ void ldsm_x4(uint32_t* r, uint32_t addr) {
    asm volatile("ldmatrix.sync.aligned.m8n8.x4.shared.b16 {%0,%1,%2,%3}, [%4];"
        : "=r"(r[0]), "=r"(r[1]), "=r"(r[2]), "=r"(r[3]) : "r"(addr));
}
__device__ __forceinline__ void mma_bf16(float* d, const uint32_t* a, const uint32_t* b) {
    asm volatile("mma.sync.aligned.m16n8k16.row.col.f32.bf16.bf16.f32 "
        "{%0,%1,%2,%3}, {%4,%5,%6,%7}, {%8,%9}, {%0,%1,%2,%3};"
        : "+f"(d[0]), "+f"(d[1]), "+f"(d[2]), "+f"(d[3])
        : "r"(a[0]), "r"(a[1]), "r"(a[2]), "r"(a[3]), "r"(b[0]), "r"(b[1]));
}

// ---------------------------------------------------------------------------
// bf16-split tensor-core SGEMM: C[M,N] = A[M,K] @ B + bias[N] (fp32 in/out)
// B element (k, c) at Bw[(c>>6)*headStride + k*rowStride + (c&63)]
// CTA 128x128, K-chunk 32; A,B -> (hi,lo) bf16; D += Ah·Bh + Ah·Bl + Al·Bh.
// ---------------------------------------------------------------------------
#define KC  32
#define STR 40   // padded smem stride (bf16 elems): 80B rows, conflict-free LDSM

__global__ void __launch_bounds__(256, 2)
gemm_mma_kernel(const float* __restrict__ A, const float* __restrict__ Bw,
                const float* __restrict__ bias, float* __restrict__ C,
                int K, int N, int headStride, int rowStride)
{
    __shared__ __nv_bfloat16 Ah[128*STR], Al[128*STR];
    __shared__ __nv_bfloat16 Bh[128*STR], Bl[128*STR];

    const int tid  = threadIdx.x;
    const int wid  = tid >> 5;
    const int lane = tid & 31;
    const int bm   = blockIdx.y * 128;
    const int bn   = blockIdx.x * 128;
    const int warp_m = wid & 3;      // 4 warps over M: 32 rows each
    const int warp_n = wid >> 2;     // 2 warps over N: 64 cols each

    float acc[2][8][4];
    #pragma unroll
    for (int i = 0; i < 2; i++)
        #pragma unroll
        for (int j = 0; j < 8; j++)
            #pragma unroll
            for (int e = 0; e < 4; e++) acc[i][j][e] = 0.f;

    // precomputed ldmatrix lane addresses (element offsets within tile arrays)
    const int a_row_off = (lane & 15) * STR + ((lane >> 4) << 3);           // + m0*STR + ks
    const int b_row_off = ((lane & 7) + ((lane >> 4) << 3)) * STR + (((lane >> 3) & 1) << 3); // + n0*STR + ks

    for (int k0 = 0; k0 < K; k0 += KC) {
        // ---- A tile: 128 x 32 fp32 -> hi/lo bf16 ----
        #pragma unroll
        for (int t = 0; t < 4; t++) {
            int idx = tid + t * 256;            // 0..1023 float4
            int m   = idx >> 3;                 // 0..127
            int kq  = (idx & 7) << 2;           // 0..28
            float4 va = *(const float4*)(A + (size_t)(bm + m) * K + k0 + kq);
            float xs[4] = {va.x, va.y, va.z, va.w};
            union { __nv_bfloat16 h[4]; u64t u; } hi, lo;
            #pragma unroll
            for (int e = 0; e < 4; e++) {
                __nv_bfloat16 h = __float2bfloat16(xs[e]);
                hi.h[e] = h;
                lo.h[e] = __float2bfloat16(xs[e] - __bfloat162float(h));
            }
            *(u64t*)&Ah[m*STR + kq] = hi.u;
            *(u64t*)&Al[m*STR + kq] = lo.u;
        }
        // ---- B tile: k 0..31 x c 0..127, stored transposed Bs[c][k] ----
        #pragma unroll
        for (int t = 0; t < 4; t++) {
            int idx = tid + t * 256;
            int k   = idx >> 5;                 // 0..31
            int c4  = (idx & 31) << 2;          // 0..124
            int c   = bn + c4;
            const float* bp = Bw + (size_t)(c >> 6) * headStride
                                 + (size_t)(k0 + k) * rowStride + (c & 63);
            float4 vb = *(const float4*)bp;
            float xs[4] = {vb.x, vb.y, vb.z, vb.w};
            #pragma unroll
            for (int e = 0; e < 4; e++) {
                __nv_bfloat16 h = __float2bfloat16(xs[e]);
                Bh[(c4 + e)*STR + k] = h;
                Bl[(c4 + e)*STR + k] = __float2bfloat16(xs[e] - __bfloat162float(h));
            }
        }
        __syncthreads();

        #pragma unroll
        for (int ks = 0; ks < KC; ks += 16) {
            uint32_t ah[2][4], al[2][4], bb[4][4];
            #pragma unroll
            for (int mt = 0; mt < 2; mt++) {
                int base = (warp_m*32 + mt*16) * STR + ks;
                ldsm_x4(ah[mt], smem_u32(&Ah[base + a_row_off]));
                ldsm_x4(al[mt], smem_u32(&Al[base + a_row_off]));
            }
            // B hi: Ah*Bh + Al*Bh
            #pragma unroll
            for (int nb = 0; nb < 4; nb++) {
                int base = (warp_n*64 + nb*16) * STR + ks;
                ldsm_x4(bb[nb], smem_u32(&Bh[base + b_row_off]));
            }
            #pragma unroll
            for (int mt = 0; mt < 2; mt++)
                #pragma unroll
                for (int nt = 0; nt < 8; nt++) {
                    mma_bf16(acc[mt][nt], ah[mt], &bb[nt>>1][(nt&1)*2]);
                    mma_bf16(acc[mt][nt], al[mt], &bb[nt>>1][(nt&1)*2]);
                }
            // B lo: Ah*Bl
            #pragma unroll
            for (int nb = 0; nb < 4; nb++) {
                int base = (warp_n*64 + nb*16) * STR + ks;
                ldsm_x4(bb[nb], smem_u32(&Bl[base + b_row_off]));
            }
            #pragma unroll
            for (int mt = 0; mt < 2; mt++)
                #pragma unroll
                for (int nt = 0; nt < 8; nt++)
                    mma_bf16(acc[mt][nt], ah[mt], &bb[nt>>1][(nt&1)*2]);
        }
        __syncthreads();
    }

    // ---- epilogue + bias ----
    #pragma unroll
    for (int mt = 0; mt < 2; mt++) {
        int r0 = bm + warp_m*32 + mt*16 + (lane >> 2);
        #pragma unroll
        for (int nt = 0; nt < 8; nt++) {
            int col = bn + warp_n*64 + nt*8 + (lane & 3)*2;
            float b0 = __ldg(bias + col), b1 = __ldg(bias + col + 1);
            float2 o0 = { acc[mt][nt][0] + b0, acc[mt][nt][1] + b1 };
            float2 o1 = { acc[mt][nt][2] + b0, acc[mt][nt][3] + b1 };
            *(float2*)(C + (size_t)r0       * N + col) = o0;
            *(float2*)(C + (size_t)(r0 + 8) * N + col) = o1;
        }
    }
}

// ---------------------------------------------------------------------------
// Per-head LayerNorm over d_head=64, in place. One warp per (b,s,n) row.
// ---------------------------------------------------------------------------
__global__ void __launch_bounds__(256)
ln_kernel(float* __restrict__ qb, float* __restrict__ kb,
          const float* __restrict__ w1, const float* __restrict__ b1,
          const float* __restrict__ w2, const float* __restrict__ b2)
{
    const int warp = threadIdx.x >> 5;
    const int lane = threadIdx.x & 31;
    const int row  = blockIdx.x * 8 + warp;

    float* base       = (blockIdx.y == 0) ? qb : kb;
    const float* w    = (blockIdx.y == 0) ? w1 : w2;
    const float* bb   = (blockIdx.y == 0) ? b1 : b2;

    float* p = base + (size_t)row * DH_;
    float x0 = p[lane];
    float x1 = p[lane + 32];
    float s  = x0 + x1;
    float sq = x0*x0 + x1*x1;
    #pragma unroll
    for (int o = 16; o > 0; o >>= 1) {
        s  += __shfl_xor_sync(0xffffffffu, s,  o);
        sq += __shfl_xor_sync(0xffffffffu, sq, o);
    }
    float mean = s * (1.0f/64.0f);
    float var  = sq * (1.0f/64.0f) - mean*mean;
    float rstd = rsqrtf(var + 1e-5f);
    p[lane]      = (x0 - mean) * rstd * w[lane]      + bb[lane];
    p[lane + 32] = (x1 - mean) * rstd * w[lane + 32] + bb[lane + 32];
}

// ---------------------------------------------------------------------------
// Causal flash attention, fp32 packed f32x2, no 1/sqrt(d) scaling.
// One query row per thread; 128 threads/CTA; K/V tiles (64x64) in SMEM.
// ---------------------------------------------------------------------------
__global__ void __launch_bounds__(128)
attn_kernel(const float* __restrict__ q, const float* __restrict__ k,
            const float* __restrict__ v, float* __restrict__ z)
{
    __shared__ float Ks[64][64];
    __shared__ float Vs[64][64];

    const int b = blockIdx.z;
    const int n = blockIdx.y;
    const int qrow = blockIdx.x * 128 + threadIdx.x;

    u64t q2[32];
    {
        const float* qp = q + (size_t)(b * SQ_ + qrow) * DM_ + n * DH_;
        #pragma unroll
        for (int i = 0; i < 16; i++) {
            F4U t; t.f = *(const float4*)(qp + i*4);
            q2[2*i]   = t.u[0];
            q2[2*i+1] = t.u[1];
        }
    }

    u64t acc2[32];
    #pragma unroll
    for (int h = 0; h < 32; h++) acc2[h] = 0ull;
    float m = -1e30f, l = 0.f;

    const int ntiles = blockIdx.x * 2 + 2;
    for (int kt = 0; kt < ntiles; kt++) {
        const int kbase = b * SQ_ + kt * 64;
        #pragma unroll
        for (int i = 0; i < 8; i++) {
            int idx = threadIdx.x + i * 128;
            int j   = idx >> 4;
            int h4  = (idx & 15) << 2;
            const size_t off = (size_t)(kbase + j) * DM_ + n * DH_ + h4;
            *(float4*)&Ks[j][h4] = *(const float4*)(k + off);
            *(float4*)&Vs[j][h4] = *(const float4*)(v + off);
        }
        __syncthreads();

        int jmax = qrow - kt * 64 + 1;
        if (jmax > 64) jmax = 64;
        for (int j = 0; j < jmax; j++) {
            const float4* Kj = (const float4*)&Ks[j][0];
            u64t s2[4] = {0ull, 0ull, 0ull, 0ull};
            #pragma unroll
            for (int t = 0; t < 16; t++) {
                F4U kk4; kk4.f = Kj[t];
                s2[(2*t)   & 3] = fma2(q2[2*t],   kk4.u[0], s2[(2*t)   & 3]);
                s2[(2*t+1) & 3] = fma2(q2[2*t+1], kk4.u[1], s2[(2*t+1) & 3]);
            }
            U2F u0, u1, u2, u3;
            u0.u = s2[0]; u1.u = s2[1]; u2.u = s2[2]; u3.u = s2[3];
            float sc = ((u0.s[0] + u0.s[1]) + (u1.s[0] + u1.s[1]))
                     + ((u2.s[0] + u2.s[1]) + (u3.s[0] + u3.s[1]));

            float mn = fmaxf(m, sc);
            if (mn > m) {
                u64t cd = dup2(__expf(m - mn));
                U2F c; c.u = cd;
                l *= c.s[0];
                #pragma unroll
                for (int h = 0; h < 32; h++) acc2[h] = mul2(cd, acc2[h]);
                m = mn;
            }
            float p = __expf(sc - mn);
            l += p;
            u64t pd = dup2(p);
            const float4* Vj = (const float4*)&Vs[j][0];
            #pragma unroll
            for (int t = 0; t < 16; t++) {
                F4U vv4; vv4.f = Vj[t];
                acc2[2*t]   = fma2(pd, vv4.u[0], acc2[2*t]);
                acc2[2*t+1] = fma2(pd, vv4.u[1], acc2[2*t+1]);
            }
        }
        __syncthreads();
    }

    u64t ivd = dup2(1.0f / l);
    float* zp = z + (size_t)(b * SQ_ + qrow) * DM_ + n * DH_;
    #pragma unroll
    for (int t = 0; t < 16; t++) {
        F4U o;
        o.u[0] = mul2(ivd, acc2[2*t]);
        o.u[1] = mul2(ivd, acc2[2*t+1]);
        *(float4*)(zp + t*4) = o.f;
    }
}

// ---------------------------------------------------------------------------
// Launch. Inputs: 0 x_q, 1 x_kv, 2 mask(ignored), 3 W_Q, 4 W_K, 5 W_V, 6 W_O,
// 7 b_Q, 8 b_K, 9 b_V, 10 b_O, 11 ln1_w, 12 ln1_b, 13 ln2_w, 14 ln2_b
// Output: [out (B,SQ,DM) | k_postLN (B,SK,NH,DH) | v (B,SK,NH,DH)]
// ---------------------------------------------------------------------------
extern "C" void kernel_launch(void* const* d_in, const int* in_sizes, int n_in,
                              void* d_out, int out_size)
{
    const float* x_q  = (const float*)d_in[0];
    const float* x_kv = (const float*)d_in[1];
    const float* W_Q  = (const float*)d_in[3];
    const float* W_K  = (const float*)d_in[4];
    const float* W_V  = (const float*)d_in[5];
    const float* W_O  = (const float*)d_in[6];
    const float* b_Q  = (const float*)d_in[7];
    const float* b_K  = (const float*)d_in[8];
    const float* b_V  = (const float*)d_in[9];
    const float* b_O  = (const float*)d_in[10];
    const float* ln1w = (const float*)d_in[11];
    const float* ln1b = (const float*)d_in[12];
    const float* ln2w = (const float*)d_in[13];
    const float* ln2b = (const float*)d_in[14];

    float* out  = (float*)d_out;
    float* kout = out  + (size_t)B_*SQ_*DM_;
    float* vout = kout + (size_t)B_*SQ_*DM_;

    float* qbuf = nullptr;
    float* zbuf = nullptr;
    cudaGetSymbolAddress((void**)&qbuf, g_q);
    cudaGetSymbolAddress((void**)&zbuf, g_z);

    dim3 gg(DM_/128, MROWS/128);   // (8, 32)

    // QKV projections (+bias). k and v land directly in their output slots.
    gemm_mma_kernel<<<gg, 256>>>(x_q,  W_Q, b_Q, qbuf, DM_, DM_, DM_*DH_, DH_);
    gemm_mma_kernel<<<gg, 256>>>(x_kv, W_K, b_K, kout, DM_, DM_, DM_*DH_, DH_);
    gemm_mma_kernel<<<gg, 256>>>(x_kv, W_V, b_V, vout, DM_, DM_, DM_*DH_, DH_);

    // Per-head LN in place: q with ln1, k with ln2.
    ln_kernel<<<dim3((MROWS*NH_)/8, 2), 256>>>(qbuf, kout, ln1w, ln1b, ln2w, ln2b);

    // Causal attention -> z
    attn_kernel<<<dim3(SQ_/128, NH_, B_), 128>>>(qbuf, kout, vout, zbuf);

    // Output projection (+b_O)
    gemm_mma_kernel<<<gg, 256>>>(zbuf, W_O, b_O, out, DM_, DM_, DH_, DM_);
}

// round 7
// speedup vs baseline: 1.6687x; 1.5378x over previous
#include <cuda_runtime.h>
#include <cuda_bf16.h>
#include <cstdint>

// Problem constants
#define B_   2
#define SQ_  2048
#define DM_  1024
#define NH_  16
#define DH_  64
#define MROWS (B_*SQ_)          // 4096
#define HELEMS ((size_t)B_*SQ_*DM_)   // 4M elems per (b,*,n-h) tensor

// Scratch (no cudaMalloc allowed)
__device__ float g_q[HELEMS];   // pre-LN q fp32, (b,s,n,h)
__device__ float g_z[HELEMS];   // attention output z, (b,s,n,h)
// bf16 hi/lo splits, head-major (b,n,s,h)
__device__ __nv_bfloat16 g_qh[HELEMS], g_ql[HELEMS];
__device__ __nv_bfloat16 g_kh[HELEMS], g_kl[HELEMS];
__device__ __nv_bfloat16 g_vh[HELEMS], g_vl[HELEMS];

typedef unsigned long long u64t;

// ---------------- mma.sync helpers (baseline PTX, HMMA pipe) ----------------
__device__ __forceinline__ uint32_t smem_u32(const void* p) {
    uint32_t a;
    asm("{ .reg .u64 t; cvta.to.shared.u64 t, %1; cvt.u32.u64 %0, t; }" : "=r"(a) : "l"(p));
    return a;
}
__device__ __forceinline__ void ldsm_x4(uint32_t* r, uint32_t addr) {
    asm volatile("ldmatrix.sync.aligned.m8n8.x4.shared.b16 {%0,%1,%2,%3}, [%4];"
        : "=r"(r[0]), "=r"(r[1]), "=r"(r[2]), "=r"(r[3]) : "r"(addr));
}
__device__ __forceinline__ void ldsm_x4_t(uint32_t* r, uint32_t addr) {
    asm volatile("ldmatrix.sync.aligned.m8n8.x4.trans.shared.b16 {%0,%1,%2,%3}, [%4];"
        : "=r"(r[0]), "=r"(r[1]), "=r"(r[2]), "=r"(r[3]) : "r"(addr));
}
__device__ __forceinline__ void mma_bf16(float* d, const uint32_t* a, const uint32_t* b) {
    asm volatile("mma.sync.aligned.m16n8k16.row.col.f32.bf16.bf16.f32 "
        "{%0,%1,%2,%3}, {%4,%5,%6,%7}, {%8,%9}, {%0,%1,%2,%3};"
        : "+f"(d[0]), "+f"(d[1]), "+f"(d[2]), "+f"(d[3])
        : "r"(a[0]), "r"(a[1]), "r"(a[2]), "r"(a[3]), "r"(b[0]), "r"(b[1]));
}
// pack two fp32 -> bf16x2 reg: 'lo' into lower half, 'hi' into upper half
__device__ __forceinline__ uint32_t pk_bf16x2(float lo, float hi) {
    uint32_t d;
    asm("cvt.rn.bf16x2.f32 %0, %1, %2;" : "=r"(d) : "f"(hi), "f"(lo));
    return d;
}

// ---------------------------------------------------------------------------
// bf16-split tensor-core SGEMM: C[M,N] = A[M,K] @ B + bias[N]  (passed R5)
// ---------------------------------------------------------------------------
#define KC  32
#define STR 40

__global__ void __launch_bounds__(256, 2)
gemm_mma_kernel(const float* __restrict__ A, const float* __restrict__ Bw,
                const float* __restrict__ bias, float* __restrict__ C,
                int K, int N, int headStride, int rowStride)
{
    __shared__ __nv_bfloat16 Ah[128*STR], Al[128*STR];
    __shared__ __nv_bfloat16 Bh[128*STR], Bl[128*STR];

    const int tid  = threadIdx.x;
    const int wid  = tid >> 5;
    const int lane = tid & 31;
    const int bm   = blockIdx.y * 128;
    const int bn   = blockIdx.x * 128;
    const int warp_m = wid & 3;
    const int warp_n = wid >> 2;

    float acc[2][8][4];
    #pragma unroll
    for (int i = 0; i < 2; i++)
        #pragma unroll
        for (int j = 0; j < 8; j++)
            #pragma unroll
            for (int e = 0; e < 4; e++) acc[i][j][e] = 0.f;

    const int a_row_off = (lane & 15) * STR + ((lane >> 4) << 3);
    const int b_row_off = ((lane & 7) + ((lane >> 4) << 3)) * STR + (((lane >> 3) & 1) << 3);

    for (int k0 = 0; k0 < K; k0 += KC) {
        #pragma unroll
        for (int t = 0; t < 4; t++) {
            int idx = tid + t * 256;
            int m   = idx >> 3;
            int kq  = (idx & 7) << 2;
            float4 va = *(const float4*)(A + (size_t)(bm + m) * K + k0 + kq);
            float xs[4] = {va.x, va.y, va.z, va.w};
            union { __nv_bfloat16 h[4]; u64t u; } hi, lo;
            #pragma unroll
            for (int e = 0; e < 4; e++) {
                __nv_bfloat16 h = __float2bfloat16(xs[e]);
                hi.h[e] = h;
                lo.h[e] = __float2bfloat16(xs[e] - __bfloat162float(h));
            }
            *(u64t*)&Ah[m*STR + kq] = hi.u;
            *(u64t*)&Al[m*STR + kq] = lo.u;
        }
        #pragma unroll
        for (int t = 0; t < 4; t++) {
            int idx = tid + t * 256;
            int k   = idx >> 5;
            int c4  = (idx & 31) << 2;
            int c   = bn + c4;
            const float* bp = Bw + (size_t)(c >> 6) * headStride
                                 + (size_t)(k0 + k) * rowStride + (c & 63);
            float4 vb = *(const float4*)bp;
            float xs[4] = {vb.x, vb.y, vb.z, vb.w};
            #pragma unroll
            for (int e = 0; e < 4; e++) {
                __nv_bfloat16 h = __float2bfloat16(xs[e]);
                Bh[(c4 + e)*STR + k] = h;
                Bl[(c4 + e)*STR + k] = __float2bfloat16(xs[e] - __bfloat162float(h));
            }
        }
        __syncthreads();

        #pragma unroll
        for (int ks = 0; ks < KC; ks += 16) {
            uint32_t ah[2][4], al[2][4], bb[4][4];
            #pragma unroll
            for (int mt = 0; mt < 2; mt++) {
                int base = (warp_m*32 + mt*16) * STR + ks;
                ldsm_x4(ah[mt], smem_u32(&Ah[base + a_row_off]));
                ldsm_x4(al[mt], smem_u32(&Al[base + a_row_off]));
            }
            #pragma unroll
            for (int nb = 0; nb < 4; nb++) {
                int base = (warp_n*64 + nb*16) * STR + ks;
                ldsm_x4(bb[nb], smem_u32(&Bh[base + b_row_off]));
            }
            #pragma unroll
            for (int mt = 0; mt < 2; mt++)
                #pragma unroll
                for (int nt = 0; nt < 8; nt++) {
                    mma_bf16(acc[mt][nt], ah[mt], &bb[nt>>1][(nt&1)*2]);
                    mma_bf16(acc[mt][nt], al[mt], &bb[nt>>1][(nt&1)*2]);
                }
            #pragma unroll
            for (int nb = 0; nb < 4; nb++) {
                int base = (warp_n*64 + nb*16) * STR + ks;
                ldsm_x4(bb[nb], smem_u32(&Bl[base + b_row_off]));
            }
            #pragma unroll
            for (int mt = 0; mt < 2; mt++)
                #pragma unroll
                for (int nt = 0; nt < 8; nt++)
                    mma_bf16(acc[mt][nt], ah[mt], &bb[nt>>1][(nt&1)*2]);
        }
        __syncthreads();
    }

    #pragma unroll
    for (int mt = 0; mt < 2; mt++) {
        int r0 = bm + warp_m*32 + mt*16 + (lane >> 2);
        #pragma unroll
        for (int nt = 0; nt < 8; nt++) {
            int col = bn + warp_n*64 + nt*8 + (lane & 3)*2;
            float b0 = __ldg(bias + col), b1 = __ldg(bias + col + 1);
            float2 o0 = { acc[mt][nt][0] + b0, acc[mt][nt][1] + b1 };
            float2 o1 = { acc[mt][nt][2] + b0, acc[mt][nt][3] + b1 };
            *(float2*)(C + (size_t)r0       * N + col) = o0;
            *(float2*)(C + (size_t)(r0 + 8) * N + col) = o1;
        }
    }
}

// ---------------------------------------------------------------------------
// Fused LN + bf16 hi/lo split conversion.
// blockIdx.y: 0 = q (ln1 -> g_qh/g_ql), 1 = k (ln2 -> kout fp32 + g_kh/g_kl),
//             2 = v (no LN -> g_vh/g_vl). One warp per (b,s,n) row.
// src layout (b,s,n,h); dst bf16 layout (b,n,s,h).
// ---------------------------------------------------------------------------
__global__ void __launch_bounds__(256)
convert_kernel(const float* __restrict__ qb, float* __restrict__ kio,
               const float* __restrict__ vb,
               const float* __restrict__ w1, const float* __restrict__ b1,
               const float* __restrict__ w2, const float* __restrict__ b2)
{
    const int warp = threadIdx.x >> 5;
    const int lane = threadIdx.x & 31;
    const int row  = blockIdx.x * 8 + warp;     // 0..65535 over (b,s,n)
    const int job  = blockIdx.y;

    const int b = row >> 15;
    const int s = (row >> 4) & (SQ_ - 1);
    const int n = row & (NH_ - 1);
    const size_t dst = (((size_t)(b * NH_ + n)) * SQ_ + s) * DH_;

    const float* src = (job == 0) ? qb : (job == 1) ? kio : vb;
    const float* p = src + (size_t)row * DH_;
    float x0 = p[lane];
    float x1 = p[lane + 32];

    if (job < 2) {
        const float* w  = (job == 0) ? w1 : w2;
        const float* bb = (job == 0) ? b1 : b2;
        float sm = x0 + x1, sq = x0*x0 + x1*x1;
        #pragma unroll
        for (int o = 16; o > 0; o >>= 1) {
            sm += __shfl_xor_sync(0xffffffffu, sm, o);
            sq += __shfl_xor_sync(0xffffffffu, sq, o);
        }
        float mean = sm * (1.0f/64.0f);
        float var  = sq * (1.0f/64.0f) - mean*mean;
        float rstd = rsqrtf(var + 1e-5f);
        x0 = (x0 - mean) * rstd * w[lane]      + bb[lane];
        x1 = (x1 - mean) * rstd * w[lane + 32] + bb[lane + 32];
    }

    __nv_bfloat16* dh = (job == 0) ? g_qh : (job == 1) ? g_kh : g_vh;
    __nv_bfloat16* dl = (job == 0) ? g_ql : (job == 1) ? g_kl : g_vl;

    __nv_bfloat16 h0 = __float2bfloat16(x0);
    __nv_bfloat16 h1 = __float2bfloat16(x1);
    dh[dst + lane]      = h0;
    dh[dst + lane + 32] = h1;
    dl[dst + lane]      = __float2bfloat16(x0 - __bfloat162float(h0));
    dl[dst + lane + 32] = __float2bfloat16(x1 - __bfloat162float(h1));

    if (job == 1) {   // k output must be post-LN fp32
        float* ko = kio + (size_t)row * DH_;
        ko[lane] = x0; ko[lane + 32] = x1;
    }
}

// ---------------------------------------------------------------------------
// Tensor-core causal flash attention (bf16 split, fp32 softmax/acc).
// CTA: 64 queries x one (b,n); 4 warps, warp = 16 query rows.
// Key tiles of 64. S = Qh·Kh + Qh·Kl + Ql·Kh; O += Ph·Vh + Pl·Vh + Ph·Vl.
// grid = (SQ/64, NH, B), 128 threads.
// ---------------------------------------------------------------------------
#define ASTR 72   // 64 + 8 pad: stride must cover the 64-wide tile (R6 bug: was 40)

__global__ void __launch_bounds__(128, 3)
attn_mma_kernel(float* __restrict__ z)
{
    __shared__ __nv_bfloat16 Ksh[64*ASTR], Ksl[64*ASTR];
    __shared__ __nv_bfloat16 Vsh[64*ASTR], Vsl[64*ASTR];

    const int tid  = threadIdx.x;
    const int wid  = tid >> 5;
    const int lane = tid & 31;
    const int qb = blockIdx.x, n = blockIdx.y, b = blockIdx.z;
    const size_t hoff = ((size_t)(b * NH_ + n)) * SQ_ * DH_;

    const int a_off = (lane & 15) * ASTR + ((lane >> 4) << 3);
    const int b_off = ((lane & 7) + ((lane >> 4) << 3)) * ASTR + (((lane >> 3) & 1) << 3);
    const int v_off = ((lane & 7) + (((lane >> 3) & 1) << 3)) * ASTR + ((lane >> 4) << 3);

    // ---- stage Q tile (64x64 hi/lo) and extract A-frags ----
    uint32_t qfh[4][4], qfl[4][4];
    {
        const __nv_bfloat16* qhp = g_qh + hoff + (size_t)qb * 64 * DH_;
        const __nv_bfloat16* qlp = g_ql + hoff + (size_t)qb * 64 * DH_;
        #pragma unroll
        for (int i = 0; i < 4; i++) {
            int idx = tid + i * 128;
            int r = idx >> 3, c8 = (idx & 7) << 3;
            *(uint4*)&Ksh[r*ASTR + c8] = *(const uint4*)(qhp + (size_t)r * DH_ + c8);
            *(uint4*)&Ksl[r*ASTR + c8] = *(const uint4*)(qlp + (size_t)r * DH_ + c8);
        }
        __syncthreads();
        #pragma unroll
        for (int ks = 0; ks < 4; ks++) {
            ldsm_x4(qfh[ks], smem_u32(&Ksh[(wid*16)*ASTR + ks*16 + a_off]));
            ldsm_x4(qfl[ks], smem_u32(&Ksl[(wid*16)*ASTR + ks*16 + a_off]));
        }
        __syncthreads();
    }

    float oacc[8][4];
    #pragma unroll
    for (int i = 0; i < 8; i++)
        #pragma unroll
        for (int e = 0; e < 4; e++) oacc[i][e] = 0.f;
    float m0 = -1e30f, m1 = -1e30f, l0 = 0.f, l1 = 0.f;

    const int rg0 = qb*64 + wid*16 + (lane >> 2);   // this thread's first row
    const int ntiles = qb + 1;

    for (int kt = 0; kt < ntiles; kt++) {
        // ---- load K/V tiles (hi/lo) ----
        {
            const __nv_bfloat16* khp = g_kh + hoff + (size_t)kt * 64 * DH_;
            const __nv_bfloat16* klp = g_kl + hoff + (size_t)kt * 64 * DH_;
            const __nv_bfloat16* vhp = g_vh + hoff + (size_t)kt * 64 * DH_;
            const __nv_bfloat16* vlp = g_vl + hoff + (size_t)kt * 64 * DH_;
            #pragma unroll
            for (int i = 0; i < 4; i++) {
                int idx = tid + i * 128;
                int r = idx >> 3, c8 = (idx & 7) << 3;
                *(uint4*)&Ksh[r*ASTR + c8] = *(const uint4*)(khp + (size_t)r * DH_ + c8);
                *(uint4*)&Ksl[r*ASTR + c8] = *(const uint4*)(klp + (size_t)r * DH_ + c8);
                *(uint4*)&Vsh[r*ASTR + c8] = *(const uint4*)(vhp + (size_t)r * DH_ + c8);
                *(uint4*)&Vsl[r*ASTR + c8] = *(const uint4*)(vlp + (size_t)r * DH_ + c8);
            }
            __syncthreads();
        }

        // ---- S = Q K^T (3-term split) ----
        float sacc[8][4];
        #pragma unroll
        for (int i = 0; i < 8; i++)
            #pragma unroll
            for (int e = 0; e < 4; e++) sacc[i][e] = 0.f;

        #pragma unroll
        for (int ks = 0; ks < 4; ks++) {
            #pragma unroll
            for (int nbp = 0; nbp < 4; nbp++) {
                uint32_t kh4[4], kl4[4];
                ldsm_x4(kh4, smem_u32(&Ksh[(nbp*16)*ASTR + ks*16 + b_off]));
                ldsm_x4(kl4, smem_u32(&Ksl[(nbp*16)*ASTR + ks*16 + b_off]));
                #pragma unroll
                for (int h = 0; h < 2; h++) {
                    int nb = nbp*2 + h;
                    mma_bf16(sacc[nb], qfh[ks], &kh4[h*2]);
                    mma_bf16(sacc[nb], qfl[ks], &kh4[h*2]);
                    mma_bf16(sacc[nb], qfh[ks], &kl4[h*2]);
                }
            }
        }

        // ---- causal mask (only diagonal tile kt == qb) ----
        if (kt == qb) {
            #pragma unroll
            for (int nb = 0; nb < 8; nb++) {
                int j = kt*64 + nb*8 + (lane & 3)*2;
                if (j     > rg0)     sacc[nb][0] = -1e30f;
                if (j + 1 > rg0)     sacc[nb][1] = -1e30f;
                if (j     > rg0 + 8) sacc[nb][2] = -1e30f;
                if (j + 1 > rg0 + 8) sacc[nb][3] = -1e30f;
            }
        }

        // ---- online softmax ----
        float t0 = -1e30f, t1 = -1e30f;
        #pragma unroll
        for (int nb = 0; nb < 8; nb++) {
            t0 = fmaxf(t0, fmaxf(sacc[nb][0], sacc[nb][1]));
            t1 = fmaxf(t1, fmaxf(sacc[nb][2], sacc[nb][3]));
        }
        t0 = fmaxf(t0, __shfl_xor_sync(0xffffffffu, t0, 1));
        t0 = fmaxf(t0, __shfl_xor_sync(0xffffffffu, t0, 2));
        t1 = fmaxf(t1, __shfl_xor_sync(0xffffffffu, t1, 1));
        t1 = fmaxf(t1, __shfl_xor_sync(0xffffffffu, t1, 2));
        float mn0 = fmaxf(m0, t0), mn1 = fmaxf(m1, t1);
        float c0 = __expf(m0 - mn0), c1 = __expf(m1 - mn1);
        m0 = mn0; m1 = mn1;

        uint32_t pah[4][4], pal[4][4];
        float rs0 = 0.f, rs1 = 0.f;
        #pragma unroll
        for (int nb = 0; nb < 8; nb++) {
            float p0 = __expf(sacc[nb][0] - mn0);
            float p1 = __expf(sacc[nb][1] - mn0);
            float p2 = __expf(sacc[nb][2] - mn1);
            float p3 = __expf(sacc[nb][3] - mn1);
            rs0 += p0 + p1; rs1 += p2 + p3;
            __nv_bfloat16 h0 = __float2bfloat16(p0), h1 = __float2bfloat16(p1);
            __nv_bfloat16 h2 = __float2bfloat16(p2), h3 = __float2bfloat16(p3);
            float q0 = p0 - __bfloat162float(h0), q1 = p1 - __bfloat162float(h1);
            float q2 = p2 - __bfloat162float(h2), q3 = p3 - __bfloat162float(h3);
            int ks = nb >> 1, sel = (nb & 1) * 2;
            pah[ks][sel]     = pk_bf16x2(__bfloat162float(h0), __bfloat162float(h1));
            pah[ks][sel + 1] = pk_bf16x2(__bfloat162float(h2), __bfloat162float(h3));
            pal[ks][sel]     = pk_bf16x2(q0, q1);
            pal[ks][sel + 1] = pk_bf16x2(q2, q3);
        }
        rs0 += __shfl_xor_sync(0xffffffffu, rs0, 1);
        rs0 += __shfl_xor_sync(0xffffffffu, rs0, 2);
        rs1 += __shfl_xor_sync(0xffffffffu, rs1, 1);
        rs1 += __shfl_xor_sync(0xffffffffu, rs1, 2);
        l0 = l0 * c0 + rs0;
        l1 = l1 * c1 + rs1;
        #pragma unroll
        for (int nb = 0; nb < 8; nb++) {
            oacc[nb][0] *= c0; oacc[nb][1] *= c0;
            oacc[nb][2] *= c1; oacc[nb][3] *= c1;
        }

        // ---- O += P V (3-term split); V B-frags via ldmatrix.trans ----
        #pragma unroll
        for (int ks = 0; ks < 4; ks++) {
            #pragma unroll
            for (int nbp = 0; nbp < 4; nbp++) {
                uint32_t vh4[4], vl4[4];
                ldsm_x4_t(vh4, smem_u32(&Vsh[(ks*16)*ASTR + nbp*16 + v_off]));
                ldsm_x4_t(vl4, smem_u32(&Vsl[(ks*16)*ASTR + nbp*16 + v_off]));
                #pragma unroll
                for (int h = 0; h < 2; h++) {
                    int nb = nbp*2 + h;
                    mma_bf16(oacc[nb], pah[ks], &vh4[h*2]);
                    mma_bf16(oacc[nb], pal[ks], &vh4[h*2]);
                    mma_bf16(oacc[nb], pah[ks], &vl4[h*2]);
                }
            }
        }
        __syncthreads();
    }

    // ---- epilogue: O / l -> z (b,s,n,h) ----
    float i0 = 1.0f / l0, i1 = 1.0f / l1;
    const int s0 = rg0;
    #pragma unroll
    for (int nb = 0; nb < 8; nb++) {
        int h = nb*8 + (lane & 3)*2;
        float2 o0 = { oacc[nb][0] * i0, oacc[nb][1] * i0 };
        float2 o1 = { oacc[nb][2] * i1, oacc[nb][3] * i1 };
        *(float2*)(z + (size_t)(b*SQ_ + s0    ) * DM_ + n*DH_ + h) = o0;
        *(float2*)(z + (size_t)(b*SQ_ + s0 + 8) * DM_ + n*DH_ + h) = o1;
    }
}

// ---------------------------------------------------------------------------
// Launch. Inputs: 0 x_q, 1 x_kv, 2 mask(ignored), 3 W_Q, 4 W_K, 5 W_V, 6 W_O,
// 7 b_Q, 8 b_K, 9 b_V, 10 b_O, 11 ln1_w, 12 ln1_b, 13 ln2_w, 14 ln2_b
// Output: [out (B,SQ,DM) | k_postLN (B,SK,NH,DH) | v (B,SK,NH,DH)]
// ---------------------------------------------------------------------------
extern "C" void kernel_launch(void* const* d_in, const int* in_sizes, int n_in,
                              void* d_out, int out_size)
{
    const float* x_q  = (const float*)d_in[0];
    const float* x_kv = (const float*)d_in[1];
    const float* W_Q  = (const float*)d_in[3];
    const float* W_K  = (const float*)d_in[4];
    const float* W_V  = (const float*)d_in[5];
    const float* W_O  = (const float*)d_in[6];
    const float* b_Q  = (const float*)d_in[7];
    const float* b_K  = (const float*)d_in[8];
    const float* b_V  = (const float*)d_in[9];
    const float* b_O  = (const float*)d_in[10];
    const float* ln1w = (const float*)d_in[11];
    const float* ln1b = (const float*)d_in[12];
    const float* ln2w = (const float*)d_in[13];
    const float* ln2b = (const float*)d_in[14];

    float* out  = (float*)d_out;
    float* kout = out  + HELEMS;
    float* vout = kout + HELEMS;

    float* qbuf = nullptr;
    float* zbuf = nullptr;
    cudaGetSymbolAddress((void**)&qbuf, g_q);
    cudaGetSymbolAddress((void**)&zbuf, g_z);

    dim3 gg(DM_/128, MROWS/128);   // (8, 32)

    // QKV projections (+bias). k and v land directly in their output slots.
    gemm_mma_kernel<<<gg, 256>>>(x_q,  W_Q, b_Q, qbuf, DM_, DM_, DM_*DH_, DH_);
    gemm_mma_kernel<<<gg, 256>>>(x_kv, W_K, b_K, kout, DM_, DM_, DM_*DH_, DH_);
    gemm_mma_kernel<<<gg, 256>>>(x_kv, W_V, b_V, vout, DM_, DM_, DM_*DH_, DH_);

    // LN + bf16 hi/lo conversion (q, k, v). k gets post-LN fp32 written back.
    convert_kernel<<<dim3((MROWS*NH_)/8, 3), 256>>>(qbuf, kout, vout,
                                                    ln1w, ln1b, ln2w, ln2b);

    // Tensor-core causal attention -> z
    attn_mma_kernel<<<dim3(SQ_/64, NH_, B_), 128>>>(zbuf);

    // Output projection (+b_O)
    gemm_mma_kernel<<<gg, 256>>>(zbuf, W_O, b_O, out, DM_, DM_, DH_, DM_);
}

// round 8
// speedup vs baseline: 2.4729x; 1.4819x over previous
#include <cuda_runtime.h>
#include <cuda_fp16.h>
#include <cstdint>

// Problem constants
#define B_   2
#define SQ_  2048
#define DM_  1024
#define NH_  16
#define DH_  64
#define MROWS (B_*SQ_)                 // 4096
#define HELEMS ((size_t)B_*SQ_*DM_)    // 4M
#define WELEMS ((size_t)NH_*DM_*DH_)   // 1M

// Scratch (no cudaMalloc allowed)
__device__ float g_q[HELEMS];                       // pre-LN q fp32 (b,s,n,h)
// fp16 hi/lo splits of inputs, row-major (rows, DM)
__device__ __half g_xqh[HELEMS],  g_xql[HELEMS];
__device__ __half g_xkvh[HELEMS], g_xkvl[HELEMS];
// fp16 weights (single precision term)
__device__ __half g_wq16[WELEMS], g_wk16[WELEMS], g_wv16[WELEMS], g_wo16[WELEMS];
// post-LN q/k hi/lo + v hi, head-major (b,n,s,h)
__device__ __half g_qh16[HELEMS], g_ql16[HELEMS];
__device__ __half g_kh16[HELEMS], g_kl16[HELEMS];
__device__ __half g_vh16[HELEMS];
// attention output hi/lo, row-major (b*s, DM)
__device__ __half g_zh16[HELEMS], g_zl16[HELEMS];

// ---------------- mma.sync helpers (baseline PTX, HMMA pipe) ----------------
__device__ __forceinline__ uint32_t smem_u32(const void* p) {
    uint32_t a;
    asm("{ .reg .u64 t; cvta.to.shared.u64 t, %1; cvt.u32.u64 %0, t; }" : "=r"(a) : "l"(p));
    return a;
}
__device__ __forceinline__ void ldsm_x4(uint32_t* r, uint32_t addr) {
    asm volatile("ldmatrix.sync.aligned.m8n8.x4.shared.b16 {%0,%1,%2,%3}, [%4];"
        : "=r"(r[0]), "=r"(r[1]), "=r"(r[2]), "=r"(r[3]) : "r"(addr));
}
__device__ __forceinline__ void ldsm_x4_t(uint32_t* r, uint32_t addr) {
    asm volatile("ldmatrix.sync.aligned.m8n8.x4.trans.shared.b16 {%0,%1,%2,%3}, [%4];"
        : "=r"(r[0]), "=r"(r[1]), "=r"(r[2]), "=r"(r[3]) : "r"(addr));
}
__device__ __forceinline__ void mma_f16(float* d, const uint32_t* a, const uint32_t* b) {
    asm volatile("mma.sync.aligned.m16n8k16.row.col.f32.f16.f16.f32 "
        "{%0,%1,%2,%3}, {%4,%5,%6,%7}, {%8,%9}, {%0,%1,%2,%3};"
        : "+f"(d[0]), "+f"(d[1]), "+f"(d[2]), "+f"(d[3])
        : "r"(a[0]), "r"(a[1]), "r"(a[2]), "r"(a[3]), "r"(b[0]), "r"(b[1]));
}
// pack two fp32 -> f16x2 reg: 'lo' into lower half, 'hi' into upper half
__device__ __forceinline__ uint32_t pk_f16x2(float lo, float hi) {
    uint32_t d;
    asm("cvt.rn.f16x2.f32 %0, %1, %2;" : "=r"(d) : "f"(hi), "f"(lo));
    return d;
}

// ---------------------------------------------------------------------------
// Prep: fp32 -> fp16 hi/lo splits (x_q, x_kv) and fp16 weights.
// ---------------------------------------------------------------------------
__global__ void __launch_bounds__(256)
prep_split(const float* __restrict__ xq, const float* __restrict__ xkv,
           const float* __restrict__ wq, const float* __restrict__ wk,
           const float* __restrict__ wv, const float* __restrict__ wo)
{
    const int job = blockIdx.y;
    const float* src; __half* dh; __half* dl; size_t n4;
    switch (job) {
        case 0: src = xq;  dh = g_xqh;  dl = g_xql;  n4 = HELEMS/4; break;
        case 1: src = xkv; dh = g_xkvh; dl = g_xkvl; n4 = HELEMS/4; break;
        case 2: src = wq;  dh = g_wq16; dl = nullptr; n4 = WELEMS/4; break;
        case 3: src = wk;  dh = g_wk16; dl = nullptr; n4 = WELEMS/4; break;
        case 4: src = wv;  dh = g_wv16; dl = nullptr; n4 = WELEMS/4; break;
        default: src = wo; dh = g_wo16; dl = nullptr; n4 = WELEMS/4; break;
    }
    for (size_t i = (size_t)blockIdx.x * 256 + threadIdx.x; i < n4;
         i += (size_t)gridDim.x * 256) {
        float4 v = ((const float4*)src)[i];
        __half2 h01 = __floats2half2_rn(v.x, v.y);
        __half2 h23 = __floats2half2_rn(v.z, v.w);
        *(__half2*)(dh + 4*i)     = h01;
        *(__half2*)(dh + 4*i + 2) = h23;
        if (dl) {
            float r0 = v.x - __low2float(h01), r1 = v.y - __high2float(h01);
            float r2 = v.z - __low2float(h23), r3 = v.w - __high2float(h23);
            *(__half2*)(dl + 4*i)     = __floats2half2_rn(r0, r1);
            *(__half2*)(dl + 4*i + 2) = __floats2half2_rn(r2, r3);
        }
    }
}

// ---------------------------------------------------------------------------
// fp16 2-term tensor-core SGEMM: C = (Ah + Al) @ B + bias, fp32 out.
// A hi/lo fp16 row-major [M,K]; B fp16 with element (k,c) at
// Bw[(c>>6)*headStride + k*rowStride + (c&63)].
// CTA 128x128, K-chunk 32, 8 warps (4m x 2n).
// ---------------------------------------------------------------------------
#define KC  32
#define STR 40

__global__ void __launch_bounds__(256, 2)
gemm_fp16_kernel(const __half* __restrict__ Ahg, const __half* __restrict__ Alg,
                 const __half* __restrict__ Bwg, const float* __restrict__ bias,
                 float* __restrict__ C, int K, int N, int headStride, int rowStride)
{
    __shared__ __half Ahs[128*STR], Als[128*STR], Bs[128*STR];

    const int tid  = threadIdx.x;
    const int wid  = tid >> 5;
    const int lane = tid & 31;
    const int bm   = blockIdx.y * 128;
    const int bn   = blockIdx.x * 128;
    const int warp_m = wid & 3;
    const int warp_n = wid >> 2;

    float acc[2][8][4];
    #pragma unroll
    for (int i = 0; i < 2; i++)
        #pragma unroll
        for (int j = 0; j < 8; j++)
            #pragma unroll
            for (int e = 0; e < 4; e++) acc[i][j][e] = 0.f;

    const int a_row_off = (lane & 15) * STR + ((lane >> 4) << 3);
    const int b_row_off = ((lane & 7) + ((lane >> 4) << 3)) * STR + (((lane >> 3) & 1) << 3);

    for (int k0 = 0; k0 < K; k0 += KC) {
        // A tiles: 128x32 halves each = 512 uint4 per array
        #pragma unroll
        for (int t = 0; t < 2; t++) {
            int idx = tid + t * 256;
            int m   = idx >> 2;
            int kq  = (idx & 3) << 3;
            *(uint4*)&Ahs[m*STR + kq] = *(const uint4*)(Ahg + (size_t)(bm + m) * K + k0 + kq);
            *(uint4*)&Als[m*STR + kq] = *(const uint4*)(Alg + (size_t)(bm + m) * K + k0 + kq);
        }
        // B tile: 32k x 128c halves, stored transposed Bs[c][k]
        #pragma unroll
        for (int t = 0; t < 4; t++) {
            int idx = tid + t * 256;
            int k   = idx >> 5;
            int c4  = (idx & 31) << 2;
            int c   = bn + c4;
            const __half* bp = Bwg + (size_t)(c >> 6) * headStride
                                   + (size_t)(k0 + k) * rowStride + (c & 63);
            __half2 p0 = *(const __half2*)bp;
            __half2 p1 = *(const __half2*)(bp + 2);
            Bs[(c4+0)*STR + k] = __low2half(p0);
            Bs[(c4+1)*STR + k] = __high2half(p0);
            Bs[(c4+2)*STR + k] = __low2half(p1);
            Bs[(c4+3)*STR + k] = __high2half(p1);
        }
        __syncthreads();

        #pragma unroll
        for (int ks = 0; ks < KC; ks += 16) {
            uint32_t ah[2][4], al[2][4], bb[4][4];
            #pragma unroll
            for (int mt = 0; mt < 2; mt++) {
                int base = (warp_m*32 + mt*16) * STR + ks;
                ldsm_x4(ah[mt], smem_u32(&Ahs[base + a_row_off]));
                ldsm_x4(al[mt], smem_u32(&Als[base + a_row_off]));
            }
            #pragma unroll
            for (int nb = 0; nb < 4; nb++) {
                int base = (warp_n*64 + nb*16) * STR + ks;
                ldsm_x4(bb[nb], smem_u32(&Bs[base + b_row_off]));
            }
            #pragma unroll
            for (int mt = 0; mt < 2; mt++)
                #pragma unroll
                for (int nt = 0; nt < 8; nt++) {
                    mma_f16(acc[mt][nt], ah[mt], &bb[nt>>1][(nt&1)*2]);
                    mma_f16(acc[mt][nt], al[mt], &bb[nt>>1][(nt&1)*2]);
                }
        }
        __syncthreads();
    }

    #pragma unroll
    for (int mt = 0; mt < 2; mt++) {
        int r0 = bm + warp_m*32 + mt*16 + (lane >> 2);
        #pragma unroll
        for (int nt = 0; nt < 8; nt++) {
            int col = bn + warp_n*64 + nt*8 + (lane & 3)*2;
            float b0 = __ldg(bias + col), b1 = __ldg(bias + col + 1);
            float2 o0 = { acc[mt][nt][0] + b0, acc[mt][nt][1] + b1 };
            float2 o1 = { acc[mt][nt][2] + b0, acc[mt][nt][3] + b1 };
            *(float2*)(C + (size_t)r0       * N + col) = o0;
            *(float2*)(C + (size_t)(r0 + 8) * N + col) = o1;
        }
    }
}

// ---------------------------------------------------------------------------
// Fused LN + fp16 split conversion. blockIdx.y: 0=q (ln1 -> qh/ql),
// 1=k (ln2 -> kout fp32 + kh/kl), 2=v (no LN -> vh only).
// src (b,s,n,h) fp32; dst fp16 head-major (b,n,s,h). One warp per row.
// ---------------------------------------------------------------------------
__global__ void __launch_bounds__(256)
convert_kernel(const float* __restrict__ qb, float* __restrict__ kio,
               const float* __restrict__ vb,
               const float* __restrict__ w1, const float* __restrict__ b1,
               const float* __restrict__ w2, const float* __restrict__ b2)
{
    const int warp = threadIdx.x >> 5;
    const int lane = threadIdx.x & 31;
    const int row  = blockIdx.x * 8 + warp;     // over (b,s,n)
    const int job  = blockIdx.y;

    const int b = row >> 15;
    const int s = (row >> 4) & (SQ_ - 1);
    const int n = row & (NH_ - 1);
    const size_t dst = (((size_t)(b * NH_ + n)) * SQ_ + s) * DH_;

    const float* src = (job == 0) ? qb : (job == 1) ? kio : vb;
    const float* p = src + (size_t)row * DH_;
    float x0 = p[lane];
    float x1 = p[lane + 32];

    if (job < 2) {
        const float* w  = (job == 0) ? w1 : w2;
        const float* bb = (job == 0) ? b1 : b2;
        float sm = x0 + x1, sq = x0*x0 + x1*x1;
        #pragma unroll
        for (int o = 16; o > 0; o >>= 1) {
            sm += __shfl_xor_sync(0xffffffffu, sm, o);
            sq += __shfl_xor_sync(0xffffffffu, sq, o);
        }
        float mean = sm * (1.0f/64.0f);
        float var  = sq * (1.0f/64.0f) - mean*mean;
        float rstd = rsqrtf(var + 1e-5f);
        x0 = (x0 - mean) * rstd * w[lane]      + bb[lane];
        x1 = (x1 - mean) * rstd * w[lane + 32] + bb[lane + 32];
    }

    __half h0 = __float2half_rn(x0);
    __half h1 = __float2half_rn(x1);

    if (job == 0) {
        g_qh16[dst + lane] = h0;  g_qh16[dst + lane + 32] = h1;
        g_ql16[dst + lane]      = __float2half_rn(x0 - __half2float(h0));
        g_ql16[dst + lane + 32] = __float2half_rn(x1 - __half2float(h1));
    } else if (job == 1) {
        g_kh16[dst + lane] = h0;  g_kh16[dst + lane + 32] = h1;
        g_kl16[dst + lane]      = __float2half_rn(x0 - __half2float(h0));
        g_kl16[dst + lane + 32] = __float2half_rn(x1 - __half2float(h1));
        float* ko = kio + (size_t)row * DH_;   // post-LN fp32 k output
        ko[lane] = x0; ko[lane + 32] = x1;
    } else {
        g_vh16[dst + lane] = h0;  g_vh16[dst + lane + 32] = h1;
    }
}

// ---------------------------------------------------------------------------
// Tensor-core causal flash attention, fp16.
// S = Qh·Kh + Ql·Kh + Qh·Kl (3-term); O += Ph·Vh + Pl·Vh (2-term, V single).
// CTA: 64 queries x one (b,n); 4 warps; key tiles of 64.
// Writes z as fp16 hi/lo to g_zh16/g_zl16, layout (b*s, DM).
// ---------------------------------------------------------------------------
#define ASTR 72

__global__ void __launch_bounds__(128, 3)
attn_mma_kernel()
{
    __shared__ __half Ksh[64*ASTR], Ksl[64*ASTR], Vsh[64*ASTR];

    const int tid  = threadIdx.x;
    const int wid  = tid >> 5;
    const int lane = tid & 31;
    const int qb = blockIdx.x, n = blockIdx.y, b = blockIdx.z;
    const size_t hoff = ((size_t)(b * NH_ + n)) * SQ_ * DH_;

    const int a_off = (lane & 15) * ASTR + ((lane >> 4) << 3);
    const int b_off = ((lane & 7) + ((lane >> 4) << 3)) * ASTR + (((lane >> 3) & 1) << 3);
    const int v_off = ((lane & 7) + (((lane >> 3) & 1) << 3)) * ASTR + ((lane >> 4) << 3);

    // ---- stage Q tile (64x64 hi/lo) and extract A-frags ----
    uint32_t qfh[4][4], qfl[4][4];
    {
        const __half* qhp = g_qh16 + hoff + (size_t)qb * 64 * DH_;
        const __half* qlp = g_ql16 + hoff + (size_t)qb * 64 * DH_;
        #pragma unroll
        for (int i = 0; i < 4; i++) {
            int idx = tid + i * 128;
            int r = idx >> 3, c8 = (idx & 7) << 3;
            *(uint4*)&Ksh[r*ASTR + c8] = *(const uint4*)(qhp + (size_t)r * DH_ + c8);
            *(uint4*)&Ksl[r*ASTR + c8] = *(const uint4*)(qlp + (size_t)r * DH_ + c8);
        }
        __syncthreads();
        #pragma unroll
        for (int ks = 0; ks < 4; ks++) {
            ldsm_x4(qfh[ks], smem_u32(&Ksh[(wid*16)*ASTR + ks*16 + a_off]));
            ldsm_x4(qfl[ks], smem_u32(&Ksl[(wid*16)*ASTR + ks*16 + a_off]));
        }
        __syncthreads();
    }

    float oacc[8][4];
    #pragma unroll
    for (int i = 0; i < 8; i++)
        #pragma unroll
        for (int e = 0; e < 4; e++) oacc[i][e] = 0.f;
    float m0 = -1e30f, m1 = -1e30f, l0 = 0.f, l1 = 0.f;

    const int rg0 = qb*64 + wid*16 + (lane >> 2);
    const int ntiles = qb + 1;

    for (int kt = 0; kt < ntiles; kt++) {
        {
            const __half* khp = g_kh16 + hoff + (size_t)kt * 64 * DH_;
            const __half* klp = g_kl16 + hoff + (size_t)kt * 64 * DH_;
            const __half* vhp = g_vh16 + hoff + (size_t)kt * 64 * DH_;
            #pragma unroll
            for (int i = 0; i < 4; i++) {
                int idx = tid + i * 128;
                int r = idx >> 3, c8 = (idx & 7) << 3;
                *(uint4*)&Ksh[r*ASTR + c8] = *(const uint4*)(khp + (size_t)r * DH_ + c8);
                *(uint4*)&Ksl[r*ASTR + c8] = *(const uint4*)(klp + (size_t)r * DH_ + c8);
                *(uint4*)&Vsh[r*ASTR + c8] = *(const uint4*)(vhp + (size_t)r * DH_ + c8);
            }
            __syncthreads();
        }

        // ---- S = Q K^T (3-term) ----
        float sacc[8][4];
        #pragma unroll
        for (int i = 0; i < 8; i++)
            #pragma unroll
            for (int e = 0; e < 4; e++) sacc[i][e] = 0.f;

        #pragma unroll
        for (int ks = 0; ks < 4; ks++) {
            #pragma unroll
            for (int nbp = 0; nbp < 4; nbp++) {
                uint32_t kh4[4], kl4[4];
                ldsm_x4(kh4, smem_u32(&Ksh[(nbp*16)*ASTR + ks*16 + b_off]));
                ldsm_x4(kl4, smem_u32(&Ksl[(nbp*16)*ASTR + ks*16 + b_off]));
                #pragma unroll
                for (int h = 0; h < 2; h++) {
                    int nb = nbp*2 + h;
                    mma_f16(sacc[nb], qfh[ks], &kh4[h*2]);
                    mma_f16(sacc[nb], qfl[ks], &kh4[h*2]);
                    mma_f16(sacc[nb], qfh[ks], &kl4[h*2]);
                }
            }
        }

        // ---- causal mask (diagonal tile only) ----
        if (kt == qb) {
            #pragma unroll
            for (int nb = 0; nb < 8; nb++) {
                int j = kt*64 + nb*8 + (lane & 3)*2;
                if (j     > rg0)     sacc[nb][0] = -1e30f;
                if (j + 1 > rg0)     sacc[nb][1] = -1e30f;
                if (j     > rg0 + 8) sacc[nb][2] = -1e30f;
                if (j + 1 > rg0 + 8) sacc[nb][3] = -1e30f;
            }
        }

        // ---- online softmax ----
        float t0 = -1e30f, t1 = -1e30f;
        #pragma unroll
        for (int nb = 0; nb < 8; nb++) {
            t0 = fmaxf(t0, fmaxf(sacc[nb][0], sacc[nb][1]));
            t1 = fmaxf(t1, fmaxf(sacc[nb][2], sacc[nb][3]));
        }
        t0 = fmaxf(t0, __shfl_xor_sync(0xffffffffu, t0, 1));
        t0 = fmaxf(t0, __shfl_xor_sync(0xffffffffu, t0, 2));
        t1 = fmaxf(t1, __shfl_xor_sync(0xffffffffu, t1, 1));
        t1 = fmaxf(t1, __shfl_xor_sync(0xffffffffu, t1, 2));
        float mn0 = fmaxf(m0, t0), mn1 = fmaxf(m1, t1);
        float c0 = __expf(m0 - mn0), c1 = __expf(m1 - mn1);
        m0 = mn0; m1 = mn1;

        uint32_t pah[4][4], pal[4][4];
        float rs0 = 0.f, rs1 = 0.f;
        #pragma unroll
        for (int nb = 0; nb < 8; nb++) {
            float p0 = __expf(sacc[nb][0] - mn0);
            float p1 = __expf(sacc[nb][1] - mn0);
            float p2 = __expf(sacc[nb][2] - mn1);
            float p3 = __expf(sacc[nb][3] - mn1);
            rs0 += p0 + p1; rs1 += p2 + p3;
            __half h0 = __float2half_rn(p0), h1 = __float2half_rn(p1);
            __half h2 = __float2half_rn(p2), h3 = __float2half_rn(p3);
            float q0 = p0 - __half2float(h0), q1 = p1 - __half2float(h1);
            float q2 = p2 - __half2float(h2), q3 = p3 - __half2float(h3);
            int ks = nb >> 1, sel = (nb & 1) * 2;
            pah[ks][sel]     = pk_f16x2(__half2float(h0), __half2float(h1));
            pah[ks][sel + 1] = pk_f16x2(__half2float(h2), __half2float(h3));
            pal[ks][sel]     = pk_f16x2(q0, q1);
            pal[ks][sel + 1] = pk_f16x2(q2, q3);
        }
        rs0 += __shfl_xor_sync(0xffffffffu, rs0, 1);
        rs0 += __shfl_xor_sync(0xffffffffu, rs0, 2);
        rs1 += __shfl_xor_sync(0xffffffffu, rs1, 1);
        rs1 += __shfl_xor_sync(0xffffffffu, rs1, 2);
        l0 = l0 * c0 + rs0;
        l1 = l1 * c1 + rs1;
        #pragma unroll
        for (int nb = 0; nb < 8; nb++) {
            oacc[nb][0] *= c0; oacc[nb][1] *= c0;
            oacc[nb][2] *= c1; oacc[nb][3] *= c1;
        }

        // ---- O += P V (2-term; V single fp16) ----
        #pragma unroll
        for (int ks = 0; ks < 4; ks++) {
            #pragma unroll
            for (int nbp = 0; nbp < 4; nbp++) {
                uint32_t vh4[4];
                ldsm_x4_t(vh4, smem_u32(&Vsh[(ks*16)*ASTR + nbp*16 + v_off]));
                #pragma unroll
                for (int h = 0; h < 2; h++) {
                    int nb = nbp*2 + h;
                    mma_f16(oacc[nb], pah[ks], &vh4[h*2]);
                    mma_f16(oacc[nb], pal[ks], &vh4[h*2]);
                }
            }
        }
        __syncthreads();
    }

    // ---- epilogue: O / l -> z fp16 hi/lo, layout (b*s, DM) ----
    float i0 = 1.0f / l0, i1 = 1.0f / l1;
    const int s0 = rg0;
    #pragma unroll
    for (int nb = 0; nb < 8; nb++) {
        int h = nb*8 + (lane & 3)*2;
        size_t z0 = (size_t)(b*SQ_ + s0    ) * DM_ + n*DH_ + h;
        size_t z1 = (size_t)(b*SQ_ + s0 + 8) * DM_ + n*DH_ + h;
        float a0 = oacc[nb][0] * i0, a1 = oacc[nb][1] * i0;
        float a2 = oacc[nb][2] * i1, a3 = oacc[nb][3] * i1;
        __half2 hh0 = __floats2half2_rn(a0, a1);
        __half2 hh1 = __floats2half2_rn(a2, a3);
        *(__half2*)(g_zh16 + z0) = hh0;
        *(__half2*)(g_zh16 + z1) = hh1;
        *(__half2*)(g_zl16 + z0) = __floats2half2_rn(a0 - __low2float(hh0), a1 - __high2float(hh0));
        *(__half2*)(g_zl16 + z1) = __floats2half2_rn(a2 - __low2float(hh1), a3 - __high2float(hh1));
    }
}

// ---------------------------------------------------------------------------
// Launch. Inputs: 0 x_q, 1 x_kv, 2 mask(ignored), 3 W_Q, 4 W_K, 5 W_V, 6 W_O,
// 7 b_Q, 8 b_K, 9 b_V, 10 b_O, 11 ln1_w, 12 ln1_b, 13 ln2_w, 14 ln2_b
// Output: [out (B,SQ,DM) | k_postLN (B,SK,NH,DH) | v (B,SK,NH,DH)]
// ---------------------------------------------------------------------------
extern "C" void kernel_launch(void* const* d_in, const int* in_sizes, int n_in,
                              void* d_out, int out_size)
{
    const float* x_q  = (const float*)d_in[0];
    const float* x_kv = (const float*)d_in[1];
    const float* W_Q  = (const float*)d_in[3];
    const float* W_K  = (const float*)d_in[4];
    const float* W_V  = (const float*)d_in[5];
    const float* W_O  = (const float*)d_in[6];
    const float* b_Q  = (const float*)d_in[7];
    const float* b_K  = (const float*)d_in[8];
    const float* b_V  = (const float*)d_in[9];
    const float* b_O  = (const float*)d_in[10];
    const float* ln1w = (const float*)d_in[11];
    const float* ln1b = (const float*)d_in[12];
    const float* ln2w = (const float*)d_in[13];
    const float* ln2b = (const float*)d_in[14];

    float* out  = (float*)d_out;
    float* kout = out  + HELEMS;
    float* vout = kout + HELEMS;

    float* qbuf = nullptr;
    cudaGetSymbolAddress((void**)&qbuf, g_q);
    __half *xqh, *xql, *xkvh, *xkvl, *wq16, *wk16, *wv16, *wo16, *zh16, *zl16;
    cudaGetSymbolAddress((void**)&xqh,  g_xqh);
    cudaGetSymbolAddress((void**)&xql,  g_xql);
    cudaGetSymbolAddress((void**)&xkvh, g_xkvh);
    cudaGetSymbolAddress((void**)&xkvl, g_xkvl);
    cudaGetSymbolAddress((void**)&wq16, g_wq16);
    cudaGetSymbolAddress((void**)&wk16, g_wk16);
    cudaGetSymbolAddress((void**)&wv16, g_wv16);
    cudaGetSymbolAddress((void**)&wo16, g_wo16);
    cudaGetSymbolAddress((void**)&zh16, g_zh16);
    cudaGetSymbolAddress((void**)&zl16, g_zl16);

    // Split inputs and weights to fp16.
    prep_split<<<dim3(512, 6), 256>>>(x_q, x_kv, W_Q, W_K, W_V, W_O);

    dim3 gg(DM_/128, MROWS/128);   // (8, 32)

    // QKV projections (+bias), fp32 outputs.
    gemm_fp16_kernel<<<gg, 256>>>(xqh,  xql,  wq16, b_Q, qbuf, DM_, DM_, DM_*DH_, DH_);
    gemm_fp16_kernel<<<gg, 256>>>(xkvh, xkvl, wk16, b_K, kout, DM_, DM_, DM_*DH_, DH_);
    gemm_fp16_kernel<<<gg, 256>>>(xkvh, xkvl, wv16, b_V, vout, DM_, DM_, DM_*DH_, DH_);

    // LN + fp16 split (q, k hi/lo; v hi). k post-LN fp32 written back.
    convert_kernel<<<dim3((MROWS*NH_)/8, 3), 256>>>(qbuf, kout, vout,
                                                    ln1w, ln1b, ln2w, ln2b);

    // Causal attention -> z fp16 hi/lo
    attn_mma_kernel<<<dim3(SQ_/64, NH_, B_), 128>>>();

    // Output projection (+b_O)
    gemm_fp16_kernel<<<gg, 256>>>(zh16, zl16, wo16, b_O, out, DM_, DM_, DH_, DM_);
}

// round 9
// speedup vs baseline: 3.2039x; 1.2956x over previous
#include <cuda_runtime.h>
#include <cuda_fp16.h>
#include <cstdint>

// Problem constants
#define B_   2
#define SQ_  2048
#define DM_  1024
#define NH_  16
#define DH_  64
#define MROWS (B_*SQ_)                 // 4096
#define HELEMS ((size_t)B_*SQ_*DM_)    // 4M
#define WELEMS ((size_t)NH_*DM_*DH_)   // 1M

// Scratch (no cudaMalloc allowed)
__device__ float g_q[HELEMS];                       // pre-LN q fp32 (b,s,n,h)
// fp16 hi/lo splits of inputs, row-major (rows, DM)
__device__ __half g_xqh[HELEMS],  g_xql[HELEMS];
__device__ __half g_xkvh[HELEMS], g_xkvl[HELEMS];
// fp16 weights hi/lo
__device__ __half g_wqh[WELEMS], g_wql[WELEMS];
__device__ __half g_wkh[WELEMS], g_wkl[WELEMS];
__device__ __half g_wvh[WELEMS], g_wvl[WELEMS];
__device__ __half g_woh[WELEMS], g_wol[WELEMS];
// post-LN q/k hi/lo + v hi, head-major (b,n,s,h)
__device__ __half g_qh16[HELEMS], g_ql16[HELEMS];
__device__ __half g_kh16[HELEMS], g_kl16[HELEMS];
__device__ __half g_vh16[HELEMS];
// attention output hi/lo, row-major (b*s, DM)
__device__ __half g_zh16[HELEMS], g_zl16[HELEMS];

// ---------------- mma.sync helpers ----------------
__device__ __forceinline__ uint32_t smem_u32(const void* p) {
    uint32_t a;
    asm("{ .reg .u64 t; cvta.to.shared.u64 t, %1; cvt.u32.u64 %0, t; }" : "=r"(a) : "l"(p));
    return a;
}
__device__ __forceinline__ void ldsm_x4(uint32_t* r, uint32_t addr) {
    asm volatile("ldmatrix.sync.aligned.m8n8.x4.shared.b16 {%0,%1,%2,%3}, [%4];"
        : "=r"(r[0]), "=r"(r[1]), "=r"(r[2]), "=r"(r[3]) : "r"(addr));
}
__device__ __forceinline__ void ldsm_x4_t(uint32_t* r, uint32_t addr) {
    asm volatile("ldmatrix.sync.aligned.m8n8.x4.trans.shared.b16 {%0,%1,%2,%3}, [%4];"
        : "=r"(r[0]), "=r"(r[1]), "=r"(r[2]), "=r"(r[3]) : "r"(addr));
}
__device__ __forceinline__ void mma_f16(float* d, const uint32_t* a, const uint32_t* b) {
    asm volatile("mma.sync.aligned.m16n8k16.row.col.f32.f16.f16.f32 "
        "{%0,%1,%2,%3}, {%4,%5,%6,%7}, {%8,%9}, {%0,%1,%2,%3};"
        : "+f"(d[0]), "+f"(d[1]), "+f"(d[2]), "+f"(d[3])
        : "r"(a[0]), "r"(a[1]), "r"(a[2]), "r"(a[3]), "r"(b[0]), "r"(b[1]));
}
__device__ __forceinline__ uint32_t pk_f16x2(float lo, float hi) {
    uint32_t d;
    asm("cvt.rn.f16x2.f32 %0, %1, %2;" : "=r"(d) : "f"(hi), "f"(lo));
    return d;
}

// ---------------------------------------------------------------------------
// Prep: fp32 -> fp16 hi/lo splits for inputs and all weights.
// ---------------------------------------------------------------------------
__global__ void __launch_bounds__(256)
prep_split(const float* __restrict__ xq, const float* __restrict__ xkv,
           const float* __restrict__ wq, const float* __restrict__ wk,
           const float* __restrict__ wv, const float* __restrict__ wo)
{
    const int job = blockIdx.y;
    const float* src; __half* dh; __half* dl; size_t n4;
    switch (job) {
        case 0: src = xq;  dh = g_xqh;  dl = g_xql;  n4 = HELEMS/4; break;
        case 1: src = xkv; dh = g_xkvh; dl = g_xkvl; n4 = HELEMS/4; break;
        case 2: src = wq;  dh = g_wqh;  dl = g_wql;  n4 = WELEMS/4; break;
        case 3: src = wk;  dh = g_wkh;  dl = g_wkl;  n4 = WELEMS/4; break;
        case 4: src = wv;  dh = g_wvh;  dl = g_wvl;  n4 = WELEMS/4; break;
        default: src = wo; dh = g_woh;  dl = g_wol;  n4 = WELEMS/4; break;
    }
    for (size_t i = (size_t)blockIdx.x * 256 + threadIdx.x; i < n4;
         i += (size_t)gridDim.x * 256) {
        float4 v = ((const float4*)src)[i];
        __half2 h01 = __floats2half2_rn(v.x, v.y);
        __half2 h23 = __floats2half2_rn(v.z, v.w);
        *(__half2*)(dh + 4*i)     = h01;
        *(__half2*)(dh + 4*i + 2) = h23;
        float r0 = v.x - __low2float(h01), r1 = v.y - __high2float(h01);
        float r2 = v.z - __low2float(h23), r3 = v.w - __high2float(h23);
        *(__half2*)(dl + 4*i)     = __floats2half2_rn(r0, r1);
        *(__half2*)(dl + 4*i + 2) = __floats2half2_rn(r2, r3);
    }
}

// ---------------------------------------------------------------------------
// fp16 3-term tensor-core SGEMM: C = (Ah+Al)@(Bh) + Ah@Bl + bias, fp32 out.
// Jobs: 0 q-proj, 1 k-proj, 2 v-proj (grid z), 3 O-proj (separate launch).
// B stored row-major [k][c] in smem; fragments via ldmatrix.trans (proven
// pattern from attention PV). B element (k,c) at Bw[(c>>6)*hs + k*rs + (c&63)].
// CTA 128x128, K-chunk 32, 8 warps (4m x 2n).
// ---------------------------------------------------------------------------
#define KC   32
#define STR  40    // A smem stride (halves)
#define BSTR 136   // B smem stride (halves): 128 + 8 pad -> conflict-free ldsm.trans

__global__ void __launch_bounds__(256, 2)
gemm3_kernel(const float* __restrict__ bQ, const float* __restrict__ bK,
             const float* __restrict__ bV, const float* __restrict__ bO,
             float* __restrict__ kout, float* __restrict__ vout,
             float* __restrict__ outp, int job_base)
{
    __shared__ __half Ahs[128*STR], Als[128*STR];
    __shared__ __half Bhs[KC*BSTR], Bls[KC*BSTR];

    const int job = job_base + blockIdx.z;
    const __half *Ahg, *Alg, *Bhg, *Blg;
    const float* bias; float* C; int hs, rs;
    switch (job) {
        case 0: Ahg = g_xqh;  Alg = g_xql;  Bhg = g_wqh; Blg = g_wql;
                bias = bQ; C = g_q;  hs = DM_*DH_; rs = DH_; break;
        case 1: Ahg = g_xkvh; Alg = g_xkvl; Bhg = g_wkh; Blg = g_wkl;
                bias = bK; C = kout; hs = DM_*DH_; rs = DH_; break;
        case 2: Ahg = g_xkvh; Alg = g_xkvl; Bhg = g_wvh; Blg = g_wvl;
                bias = bV; C = vout; hs = DM_*DH_; rs = DH_; break;
        default: Ahg = g_zh16; Alg = g_zl16; Bhg = g_woh; Blg = g_wol;
                bias = bO; C = outp; hs = DH_; rs = DM_; break;
    }

    const int tid  = threadIdx.x;
    const int wid  = tid >> 5;
    const int lane = tid & 31;
    const int bm   = blockIdx.y * 128;
    const int bn   = blockIdx.x * 128;
    const int warp_m = wid & 3;
    const int warp_n = wid >> 2;

    float acc[2][8][4];
    #pragma unroll
    for (int i = 0; i < 2; i++)
        #pragma unroll
        for (int j = 0; j < 8; j++)
            #pragma unroll
            for (int e = 0; e < 4; e++) acc[i][j][e] = 0.f;

    const int a_off   = (lane & 15) * STR + ((lane >> 4) << 3);
    const int b_off_t = ((lane & 7) + (((lane >> 3) & 1) << 3)) * BSTR + ((lane >> 4) << 3);

    for (int k0 = 0; k0 < DM_; k0 += KC) {
        // A tiles: 128x32 halves each, vectorized
        #pragma unroll
        for (int t = 0; t < 2; t++) {
            int idx = tid + t * 256;
            int m   = idx >> 2;
            int kq  = (idx & 3) << 3;
            *(uint4*)&Ahs[m*STR + kq] = *(const uint4*)(Ahg + (size_t)(bm + m) * DM_ + k0 + kq);
            *(uint4*)&Als[m*STR + kq] = *(const uint4*)(Alg + (size_t)(bm + m) * DM_ + k0 + kq);
        }
        // B tiles: 32k x 128c halves, row-major [k][c], vectorized uint4
        #pragma unroll
        for (int t = 0; t < 2; t++) {
            int idx = tid + t * 256;        // 0..511
            int k   = idx >> 4;             // 0..31
            int c8  = (idx & 15) << 3;      // 0..120
            int c   = bn + c8;
            size_t off = (size_t)(c >> 6) * hs + (size_t)(k0 + k) * rs + (c & 63);
            *(uint4*)&Bhs[k*BSTR + c8] = *(const uint4*)(Bhg + off);
            *(uint4*)&Bls[k*BSTR + c8] = *(const uint4*)(Blg + off);
        }
        __syncthreads();

        #pragma unroll
        for (int ks = 0; ks < KC; ks += 16) {
            uint32_t ah[2][4], al[2][4], bb[4][4];
            #pragma unroll
            for (int mt = 0; mt < 2; mt++) {
                int base = (warp_m*32 + mt*16) * STR + ks;
                ldsm_x4(ah[mt], smem_u32(&Ahs[base + a_off]));
                ldsm_x4(al[mt], smem_u32(&Als[base + a_off]));
            }
            // B hi fragments (trans): terms Ah·Bh + Al·Bh
            #pragma unroll
            for (int nb = 0; nb < 4; nb++) {
                int base = ks*BSTR + warp_n*64 + nb*16;
                ldsm_x4_t(bb[nb], smem_u32(&Bhs[base + b_off_t]));
            }
            #pragma unroll
            for (int mt = 0; mt < 2; mt++)
                #pragma unroll
                for (int nt = 0; nt < 8; nt++) {
                    mma_f16(acc[mt][nt], ah[mt], &bb[nt>>1][(nt&1)*2]);
                    mma_f16(acc[mt][nt], al[mt], &bb[nt>>1][(nt&1)*2]);
                }
            // B lo fragments (reuse regs): term Ah·Bl
            #pragma unroll
            for (int nb = 0; nb < 4; nb++) {
                int base = ks*BSTR + warp_n*64 + nb*16;
                ldsm_x4_t(bb[nb], smem_u32(&Bls[base + b_off_t]));
            }
            #pragma unroll
            for (int mt = 0; mt < 2; mt++)
                #pragma unroll
                for (int nt = 0; nt < 8; nt++)
                    mma_f16(acc[mt][nt], ah[mt], &bb[nt>>1][(nt&1)*2]);
        }
        __syncthreads();
    }

    #pragma unroll
    for (int mt = 0; mt < 2; mt++) {
        int r0 = bm + warp_m*32 + mt*16 + (lane >> 2);
        #pragma unroll
        for (int nt = 0; nt < 8; nt++) {
            int col = bn + warp_n*64 + nt*8 + (lane & 3)*2;
            float b0 = __ldg(bias + col), b1 = __ldg(bias + col + 1);
            float2 o0 = { acc[mt][nt][0] + b0, acc[mt][nt][1] + b1 };
            float2 o1 = { acc[mt][nt][2] + b0, acc[mt][nt][3] + b1 };
            *(float2*)(C + (size_t)r0       * DM_ + col) = o0;
            *(float2*)(C + (size_t)(r0 + 8) * DM_ + col) = o1;
        }
    }
}

// ---------------------------------------------------------------------------
// Fused LN + fp16 split conversion. blockIdx.y: 0=q (ln1 -> qh/ql),
// 1=k (ln2 -> kout fp32 + kh/kl), 2=v (no LN -> vh only).
// ---------------------------------------------------------------------------
__global__ void __launch_bounds__(256)
convert_kernel(const float* __restrict__ qb, float* __restrict__ kio,
               const float* __restrict__ vb,
               const float* __restrict__ w1, const float* __restrict__ b1,
               const float* __restrict__ w2, const float* __restrict__ b2)
{
    const int warp = threadIdx.x >> 5;
    const int lane = threadIdx.x & 31;
    const int row  = blockIdx.x * 8 + warp;
    const int job  = blockIdx.y;

    const int b = row >> 15;
    const int s = (row >> 4) & (SQ_ - 1);
    const int n = row & (NH_ - 1);
    const size_t dst = (((size_t)(b * NH_ + n)) * SQ_ + s) * DH_;

    const float* src = (job == 0) ? qb : (job == 1) ? kio : vb;
    const float* p = src + (size_t)row * DH_;
    float x0 = p[lane];
    float x1 = p[lane + 32];

    if (job < 2) {
        const float* w  = (job == 0) ? w1 : w2;
        const float* bb = (job == 0) ? b1 : b2;
        float sm = x0 + x1, sq = x0*x0 + x1*x1;
        #pragma unroll
        for (int o = 16; o > 0; o >>= 1) {
            sm += __shfl_xor_sync(0xffffffffu, sm, o);
            sq += __shfl_xor_sync(0xffffffffu, sq, o);
        }
        float mean = sm * (1.0f/64.0f);
        float var  = sq * (1.0f/64.0f) - mean*mean;
        float rstd = rsqrtf(var + 1e-5f);
        x0 = (x0 - mean) * rstd * w[lane]      + bb[lane];
        x1 = (x1 - mean) * rstd * w[lane + 32] + bb[lane + 32];
    }

    __half h0 = __float2half_rn(x0);
    __half h1 = __float2half_rn(x1);

    if (job == 0) {
        g_qh16[dst + lane] = h0;  g_qh16[dst + lane + 32] = h1;
        g_ql16[dst + lane]      = __float2half_rn(x0 - __half2float(h0));
        g_ql16[dst + lane + 32] = __float2half_rn(x1 - __half2float(h1));
    } else if (job == 1) {
        g_kh16[dst + lane] = h0;  g_kh16[dst + lane + 32] = h1;
        g_kl16[dst + lane]      = __float2half_rn(x0 - __half2float(h0));
        g_kl16[dst + lane + 32] = __float2half_rn(x1 - __half2float(h1));
        float* ko = kio + (size_t)row * DH_;
        ko[lane] = x0; ko[lane + 32] = x1;
    } else {
        g_vh16[dst + lane] = h0;  g_vh16[dst + lane + 32] = h1;
    }
}

// ---------------------------------------------------------------------------
// Tensor-core causal flash attention, fp16 (unchanged from R8 pass).
// S 3-term; PV 2-term (V single). Writes z fp16 hi/lo.
// ---------------------------------------------------------------------------
#define ASTR 72

__global__ void __launch_bounds__(128, 3)
attn_mma_kernel()
{
    __shared__ __half Ksh[64*ASTR], Ksl[64*ASTR], Vsh[64*ASTR];

    const int tid  = threadIdx.x;
    const int wid  = tid >> 5;
    const int lane = tid & 31;
    const int qb = blockIdx.x, n = blockIdx.y, b = blockIdx.z;
    const size_t hoff = ((size_t)(b * NH_ + n)) * SQ_ * DH_;

    const int a_off = (lane & 15) * ASTR + ((lane >> 4) << 3);
    const int b_off = ((lane & 7) + ((lane >> 4) << 3)) * ASTR + (((lane >> 3) & 1) << 3);
    const int v_off = ((lane & 7) + (((lane >> 3) & 1) << 3)) * ASTR + ((lane >> 4) << 3);

    uint32_t qfh[4][4], qfl[4][4];
    {
        const __half* qhp = g_qh16 + hoff + (size_t)qb * 64 * DH_;
        const __half* qlp = g_ql16 + hoff + (size_t)qb * 64 * DH_;
        #pragma unroll
        for (int i = 0; i < 4; i++) {
            int idx = tid + i * 128;
            int r = idx >> 3, c8 = (idx & 7) << 3;
            *(uint4*)&Ksh[r*ASTR + c8] = *(const uint4*)(qhp + (size_t)r * DH_ + c8);
            *(uint4*)&Ksl[r*ASTR + c8] = *(const uint4*)(qlp + (size_t)r * DH_ + c8);
        }
        __syncthreads();
        #pragma unroll
        for (int ks = 0; ks < 4; ks++) {
            ldsm_x4(qfh[ks], smem_u32(&Ksh[(wid*16)*ASTR + ks*16 + a_off]));
            ldsm_x4(qfl[ks], smem_u32(&Ksl[(wid*16)*ASTR + ks*16 + a_off]));
        }
        __syncthreads();
    }

    float oacc[8][4];
    #pragma unroll
    for (int i = 0; i < 8; i++)
        #pragma unroll
        for (int e = 0; e < 4; e++) oacc[i][e] = 0.f;
    float m0 = -1e30f, m1 = -1e30f, l0 = 0.f, l1 = 0.f;

    const int rg0 = qb*64 + wid*16 + (lane >> 2);
    const int ntiles = qb + 1;

    for (int kt = 0; kt < ntiles; kt++) {
        {
            const __half* khp = g_kh16 + hoff + (size_t)kt * 64 * DH_;
            const __half* klp = g_kl16 + hoff + (size_t)kt * 64 * DH_;
            const __half* vhp = g_vh16 + hoff + (size_t)kt * 64 * DH_;
            #pragma unroll
            for (int i = 0; i < 4; i++) {
                int idx = tid + i * 128;
                int r = idx >> 3, c8 = (idx & 7) << 3;
                *(uint4*)&Ksh[r*ASTR + c8] = *(const uint4*)(khp + (size_t)r * DH_ + c8);
                *(uint4*)&Ksl[r*ASTR + c8] = *(const uint4*)(klp + (size_t)r * DH_ + c8);
                *(uint4*)&Vsh[r*ASTR + c8] = *(const uint4*)(vhp + (size_t)r * DH_ + c8);
            }
            __syncthreads();
        }

        float sacc[8][4];
        #pragma unroll
        for (int i = 0; i < 8; i++)
            #pragma unroll
            for (int e = 0; e < 4; e++) sacc[i][e] = 0.f;

        #pragma unroll
        for (int ks = 0; ks < 4; ks++) {
            #pragma unroll
            for (int nbp = 0; nbp < 4; nbp++) {
                uint32_t kh4[4], kl4[4];
                ldsm_x4(kh4, smem_u32(&Ksh[(nbp*16)*ASTR + ks*16 + b_off]));
                ldsm_x4(kl4, smem_u32(&Ksl[(nbp*16)*ASTR + ks*16 + b_off]));
                #pragma unroll
                for (int h = 0; h < 2; h++) {
                    int nb = nbp*2 + h;
                    mma_f16(sacc[nb], qfh[ks], &kh4[h*2]);
                    mma_f16(sacc[nb], qfl[ks], &kh4[h*2]);
                    mma_f16(sacc[nb], qfh[ks], &kl4[h*2]);
                }
            }
        }

        if (kt == qb) {
            #pragma unroll
            for (int nb = 0; nb < 8; nb++) {
                int j = kt*64 + nb*8 + (lane & 3)*2;
                if (j     > rg0)     sacc[nb][0] = -1e30f;
                if (j + 1 > rg0)     sacc[nb][1] = -1e30f;
                if (j     > rg0 + 8) sacc[nb][2] = -1e30f;
                if (j + 1 > rg0 + 8) sacc[nb][3] = -1e30f;
            }
        }

        float t0 = -1e30f, t1 = -1e30f;
        #pragma unroll
        for (int nb = 0; nb < 8; nb++) {
            t0 = fmaxf(t0, fmaxf(sacc[nb][0], sacc[nb][1]));
            t1 = fmaxf(t1, fmaxf(sacc[nb][2], sacc[nb][3]));
        }
        t0 = fmaxf(t0, __shfl_xor_sync(0xffffffffu, t0, 1));
        t0 = fmaxf(t0, __shfl_xor_sync(0xffffffffu, t0, 2));
        t1 = fmaxf(t1, __shfl_xor_sync(0xffffffffu, t1, 1));
        t1 = fmaxf(t1, __shfl_xor_sync(0xffffffffu, t1, 2));
        float mn0 = fmaxf(m0, t0), mn1 = fmaxf(m1, t1);
        float c0 = __expf(m0 - mn0), c1 = __expf(m1 - mn1);
        m0 = mn0; m1 = mn1;

        uint32_t pah[4][4], pal[4][4];
        float rs0 = 0.f, rs1 = 0.f;
        #pragma unroll
        for (int nb = 0; nb < 8; nb++) {
            float p0 = __expf(sacc[nb][0] - mn0);
            float p1 = __expf(sacc[nb][1] - mn0);
            float p2 = __expf(sacc[nb][2] - mn1);
            float p3 = __expf(sacc[nb][3] - mn1);
            rs0 += p0 + p1; rs1 += p2 + p3;
            __half h0 = __float2half_rn(p0), h1 = __float2half_rn(p1);
            __half h2 = __float2half_rn(p2), h3 = __float2half_rn(p3);
            float q0 = p0 - __half2float(h0), q1 = p1 - __half2float(h1);
            float q2 = p2 - __half2float(h2), q3 = p3 - __half2float(h3);
            int ks = nb >> 1, sel = (nb & 1) * 2;
            pah[ks][sel]     = pk_f16x2(__half2float(h0), __half2float(h1));
            pah[ks][sel + 1] = pk_f16x2(__half2float(h2), __half2float(h3));
            pal[ks][sel]     = pk_f16x2(q0, q1);
            pal[ks][sel + 1] = pk_f16x2(q2, q3);
        }
        rs0 += __shfl_xor_sync(0xffffffffu, rs0, 1);
        rs0 += __shfl_xor_sync(0xffffffffu, rs0, 2);
        rs1 += __shfl_xor_sync(0xffffffffu, rs1, 1);
        rs1 += __shfl_xor_sync(0xffffffffu, rs1, 2);
        l0 = l0 * c0 + rs0;
        l1 = l1 * c1 + rs1;
        #pragma unroll
        for (int nb = 0; nb < 8; nb++) {
            oacc[nb][0] *= c0; oacc[nb][1] *= c0;
            oacc[nb][2] *= c1; oacc[nb][3] *= c1;
        }

        #pragma unroll
        for (int ks = 0; ks < 4; ks++) {
            #pragma unroll
            for (int nbp = 0; nbp < 4; nbp++) {
                uint32_t vh4[4];
                ldsm_x4_t(vh4, smem_u32(&Vsh[(ks*16)*ASTR + nbp*16 + v_off]));
                #pragma unroll
                for (int h = 0; h < 2; h++) {
                    int nb = nbp*2 + h;
                    mma_f16(oacc[nb], pah[ks], &vh4[h*2]);
                    mma_f16(oacc[nb], pal[ks], &vh4[h*2]);
                }
            }
        }
        __syncthreads();
    }

    float i0 = 1.0f / l0, i1 = 1.0f / l1;
    const int s0 = rg0;
    #pragma unroll
    for (int nb = 0; nb < 8; nb++) {
        int h = nb*8 + (lane & 3)*2;
        size_t z0 = (size_t)(b*SQ_ + s0    ) * DM_ + n*DH_ + h;
        size_t z1 = (size_t)(b*SQ_ + s0 + 8) * DM_ + n*DH_ + h;
        float a0 = oacc[nb][0] * i0, a1 = oacc[nb][1] * i0;
        float a2 = oacc[nb][2] * i1, a3 = oacc[nb][3] * i1;
        __half2 hh0 = __floats2half2_rn(a0, a1);
        __half2 hh1 = __floats2half2_rn(a2, a3);
        *(__half2*)(g_zh16 + z0) = hh0;
        *(__half2*)(g_zh16 + z1) = hh1;
        *(__half2*)(g_zl16 + z0) = __floats2half2_rn(a0 - __low2float(hh0), a1 - __high2float(hh0));
        *(__half2*)(g_zl16 + z1) = __floats2half2_rn(a2 - __low2float(hh1), a3 - __high2float(hh1));
    }
}

// ---------------------------------------------------------------------------
// Launch. Inputs: 0 x_q, 1 x_kv, 2 mask(ignored), 3 W_Q, 4 W_K, 5 W_V, 6 W_O,
// 7 b_Q, 8 b_K, 9 b_V, 10 b_O, 11 ln1_w, 12 ln1_b, 13 ln2_w, 14 ln2_b
// Output: [out (B,SQ,DM) | k_postLN (B,SK,NH,DH) | v (B,SK,NH,DH)]
// ---------------------------------------------------------------------------
extern "C" void kernel_launch(void* const* d_in, const int* in_sizes, int n_in,
                              void* d_out, int out_size)
{
    const float* x_q  = (const float*)d_in[0];
    const float* x_kv = (const float*)d_in[1];
    const float* W_Q  = (const float*)d_in[3];
    const float* W_K  = (const float*)d_in[4];
    const float* W_V  = (const float*)d_in[5];
    const float* W_O  = (const float*)d_in[6];
    const float* b_Q  = (const float*)d_in[7];
    const float* b_K  = (const float*)d_in[8];
    const float* b_V  = (const float*)d_in[9];
    const float* b_O  = (const float*)d_in[10];
    const float* ln1w = (const float*)d_in[11];
    const float* ln1b = (const float*)d_in[12];
    const float* ln2w = (const float*)d_in[13];
    const float* ln2b = (const float*)d_in[14];

    float* out  = (float*)d_out;
    float* kout = out  + HELEMS;
    float* vout = kout + HELEMS;

    float* qbuf = nullptr;
    cudaGetSymbolAddress((void**)&qbuf, g_q);

    // Split inputs and weights to fp16 hi/lo.
    prep_split<<<dim3(512, 6), 256>>>(x_q, x_kv, W_Q, W_K, W_V, W_O);

    // Merged QKV projections (+bias), 3-term, fp32 outputs.
    gemm3_kernel<<<dim3(DM_/128, MROWS/128, 3), 256>>>(b_Q, b_K, b_V, b_O,
                                                       kout, vout, out, 0);

    // LN + fp16 split (q, k hi/lo; v hi). k post-LN fp32 written back.
    convert_kernel<<<dim3((MROWS*NH_)/8, 3), 256>>>(qbuf, kout, vout,
                                                    ln1w, ln1b, ln2w, ln2b);

    // Causal attention -> z fp16 hi/lo
    attn_mma_kernel<<<dim3(SQ_/64, NH_, B_), 128>>>();

    // Output projection (+b_O), 3-term.
    gemm3_kernel<<<dim3(DM_/128, MROWS/128, 1), 256>>>(b_Q, b_K, b_V, b_O,
                                                       kout, vout, out, 3);
}